// round 1
// baseline (speedup 1.0000x reference)
#include <cuda_runtime.h>
#include <math.h>

#define HH 256
#define WW 256
#define CC 128
#define BIGF 1000000000.0f

// ---------------- device scratch (static, no allocation) ----------------
__device__ float g_cost[HH*WW*8];     // cost[p][dir]
__device__ float g_dist[2][HH*WW];    // ping-pong distance buffers
__device__ float g_geo [HH*WW];
__device__ float g_var [HH*WW];
__device__ float g_abs2[HH*WW];
__device__ float g_omega[HH*WW];
__device__ float g_endlf[64];
__device__ float g_scal[3];           // softplus(delta, gamma, beta)

__constant__ float cw1[CC*32];
__constant__ float cb1[32];
__constant__ float cw2[32];
__constant__ float cb2v[1];

__device__ __forceinline__ float softplusf(float x){
    return x > 30.0f ? x : log1pf(expf(x));
}

// ---------------- kernel 0: scalars + end-pixel lo-freq features ----------------
__global__ void k0(const float* __restrict__ f, const float* dl, const float* gm,
                   const float* bt, const int* __restrict__ endn){
    int t = threadIdx.x;
    if (t == 0){
        g_scal[0] = softplusf(*dl);
        g_scal[1] = softplusf(*gm);
        g_scal[2] = softplusf(*bt);
    }
    int e = endn[0]*WW + endn[1];
    if (t < 64) g_endlf[t] = f[(size_t)e*CC + t];
}

// ---------------- cost grid: warp per pixel ----------------
__global__ void cost_k(const float* __restrict__ f, float* __restrict__ out){
    int warp = threadIdx.x >> 5;
    int lane = threadIdx.x & 31;
    int px = blockIdx.x*8 + warp;
    int h = px >> 8, w = px & 255;

    const float4* fp = (const float4*)(f + (size_t)px*CC);
    float4 a = fp[lane];
    float ss = a.x*a.x + a.y*a.y + a.z*a.z + a.w*a.w;
    #pragma unroll
    for (int o=16;o;o>>=1) ss += __shfl_xor_sync(0xffffffffu, ss, o);
    float invp = 1.0f / fmaxf(sqrtf(ss), 1e-12f);

    const int dxs[8] = {-1,-1,-1, 0, 0, 1, 1, 1};
    const int dys[8] = {-1, 0, 1,-1, 1,-1, 0, 1};
    float res[8];
    #pragma unroll
    for (int i=0;i<8;i++){
        int nh = h + dxs[i], nw = w + dys[i];
        if ((unsigned)nh < HH && (unsigned)nw < WW){
            const float4* np = (const float4*)(f + (size_t)(nh*WW+nw)*CC);
            float4 b = np[lane];
            float d  = a.x*b.x + a.y*b.y + a.z*b.z + a.w*b.w;
            float s2 = b.x*b.x + b.y*b.y + b.z*b.z + b.w*b.w;
            #pragma unroll
            for (int o=16;o;o>>=1){
                d  += __shfl_xor_sync(0xffffffffu, d,  o);
                s2 += __shfl_xor_sync(0xffffffffu, s2, o);
            }
            res[i] = 1.0f - d * invp / fmaxf(sqrtf(s2), 1e-12f);
        } else {
            res[i] = BIGF;
        }
    }
    if (lane == 0){
        #pragma unroll
        for (int i=0;i<8;i++){
            g_cost[(size_t)px*8 + i] = res[i];
            out[(size_t)px*10 + 1 + i] = res[i];
        }
    }
}

// ---------------- heuristic tile: sobel + var(3x3) + absorption ----------------
__global__ void heur_tile(const float* __restrict__ f){
    __shared__ float s[324*17];             // 18x18 cells x 16 channels, pad 17
    int tid = threadIdx.x;
    int tx = tid & 15, ty = tid >> 4;
    int bh = blockIdx.y*16, bw = blockIdx.x*16;

    float geo = 0.0f, var = 0.0f, ab2 = 0.0f;

    for (int ck = 0; ck < 8; ck++){
        int c0 = ck*16;
        __syncthreads();
        for (int idx = tid; idx < 1296; idx += 256){
            int cell = idx >> 2, q = idx & 3;
            int r = cell / 18, col = cell % 18;
            int gh = bh + r - 1, gw = bw + col - 1;
            float4 v = make_float4(0.f,0.f,0.f,0.f);
            if ((unsigned)gh < HH && (unsigned)gw < WW)
                v = *(const float4*)(f + (size_t)(gh*WW+gw)*CC + c0 + q*4);
            float* sp = s + cell*17 + q*4;
            sp[0]=v.x; sp[1]=v.y; sp[2]=v.z; sp[3]=v.w;
        }
        __syncthreads();

        int base = (ty+1)*18 + (tx+1);
        #pragma unroll
        for (int ch = 0; ch < 16; ch++){
            float v00 = s[(base-19)*17+ch], v01 = s[(base-18)*17+ch], v02 = s[(base-17)*17+ch];
            float v10 = s[(base- 1)*17+ch], v11 = s[(base   )*17+ch], v12 = s[(base+ 1)*17+ch];
            float v20 = s[(base+17)*17+ch], v21 = s[(base+18)*17+ch], v22 = s[(base+19)*17+ch];
            float gx = (v02 - v00) + 2.0f*(v12 - v10) + (v22 - v20);
            float gy = (v20 - v00) + 2.0f*(v21 - v01) + (v22 - v02);
            geo += sqrtf(gx*gx + gy*gy);
            int c = c0 + ch;
            if (c >= 64){
                float xs = v00+v01+v02+v10+v11+v12+v20+v21+v22;
                float x2 = v00*v00+v01*v01+v02*v02+v10*v10+v11*v11+v12*v12+v20*v20+v21*v21+v22*v22;
                float m1 = xs * (1.0f/9.0f);
                var += x2 * (1.0f/9.0f) - m1*m1;
            } else {
                float d = v11 - g_endlf[c];
                ab2 += d*d;
            }
        }
    }
    int px = (bh+ty)*WW + (bw+tx);
    g_geo [px] = geo * (1.0f/128.0f);
    g_var [px] = var;
    g_abs2[px] = ab2;
}

// ---------------- MLP: one thread per pixel, W1 in constant bank ----------------
__global__ void mlp_k(const float* __restrict__ f){
    __shared__ float sf[256*33];           // 256 pixels x 32 channels, pad 33
    int tid = threadIdx.x;
    int pxbase = blockIdx.x*256;

    float acc[32];
    #pragma unroll
    for (int j=0;j<32;j++) acc[j] = cb1[j];

    #pragma unroll
    for (int ck = 0; ck < 4; ck++){
        int c0 = ck*32;
        __syncthreads();
        for (int idx = tid; idx < 2048; idx += 256){
            int p = idx >> 3, q = idx & 7;
            float4 v = *(const float4*)(f + (size_t)(pxbase+p)*CC + c0 + q*4);
            float* sp = sf + p*33 + q*4;
            sp[0]=v.x; sp[1]=v.y; sp[2]=v.z; sp[3]=v.w;
        }
        __syncthreads();
        #pragma unroll
        for (int c = 0; c < 32; c++){
            float fc = sf[tid*33 + c];
            #pragma unroll
            for (int j = 0; j < 32; j++)
                acc[j] = fmaf(fc, cw1[(c0+c)*32 + j], acc[j]);
        }
    }
    float z = cb2v[0];
    #pragma unroll
    for (int j=0;j<32;j++) z = fmaf(fmaxf(acc[j], 0.0f), cw2[j], z);
    g_omega[pxbase + tid] = 1.0f / (1.0f + expf(-z));
}

// ---------------- distance init ----------------
__global__ void dist_init(const int* __restrict__ startn){
    int idx = blockIdx.x*256 + threadIdx.x;
    int s = startn[0]*WW + startn[1];
    g_dist[0][idx] = (idx == s) ? 0.0f : BIGF;
}

// ---------------- fused K=8 Jacobi relaxation, 32x32 tile + 8 halo ----------------
__global__ void __launch_bounds__(576,1) dist_relax(int sbuf){
    __shared__ float sd[2][50][52];
    const float* __restrict__ src = g_dist[sbuf];
    float*       __restrict__ dst = g_dist[sbuf^1];

    int tid = threadIdx.x;            // 0..575
    int tx = tid % 24, ty = tid / 24; // 24x24 threads, 2x2 cells each -> 48x48 region
    int bh = blockIdx.y*32 - 8, bw = blockIdx.x*32 - 8;

    for (int idx = tid; idx < 50*52; idx += 576){
        int r = idx / 52, c = idx % 52;
        float v = BIGF;
        if (r >= 1 && r < 49 && c >= 1 && c < 49){
            int gh = bh + r - 1, gw = bw + c - 1;
            if ((unsigned)gh < HH && (unsigned)gw < WW) v = src[gh*WW + gw];
        }
        sd[0][r][c] = v;
        sd[1][r][c] = BIGF;
    }

    // own-cell costs in registers: cost[p][j] pairs with neighbor p + d_j
    float cst[2][2][8];
    #pragma unroll
    for (int a=0;a<2;a++)
    #pragma unroll
    for (int b=0;b<2;b++){
        int gh = bh + 2*ty + a, gw = bw + 2*tx + b;
        if ((unsigned)gh < HH && (unsigned)gw < WW){
            const float4* cp = (const float4*)(g_cost + (size_t)(gh*WW+gw)*8);
            float4 u = cp[0], w = cp[1];
            cst[a][b][0]=u.x; cst[a][b][1]=u.y; cst[a][b][2]=u.z; cst[a][b][3]=u.w;
            cst[a][b][4]=w.x; cst[a][b][5]=w.y; cst[a][b][6]=w.z; cst[a][b][7]=w.w;
        } else {
            #pragma unroll
            for (int i=0;i<8;i++) cst[a][b][i] = BIGF;
        }
    }

    int cur = 0;
    #pragma unroll 1
    for (int it = 0; it < 8; it++){
        __syncthreads();
        float p[4][4];
        #pragma unroll
        for (int i=0;i<4;i++)
            #pragma unroll
            for (int j=0;j<4;j++)
                p[i][j] = sd[cur][2*ty+i][2*tx+j];
        #pragma unroll
        for (int a=0;a<2;a++)
            #pragma unroll
            for (int b=0;b<2;b++){
                float v = p[a+1][b+1];
                v = fminf(v, p[a  ][b  ] + cst[a][b][0]);  // (-1,-1)
                v = fminf(v, p[a  ][b+1] + cst[a][b][1]);  // (-1, 0)
                v = fminf(v, p[a  ][b+2] + cst[a][b][2]);  // (-1, 1)
                v = fminf(v, p[a+1][b  ] + cst[a][b][3]);  // ( 0,-1)
                v = fminf(v, p[a+1][b+2] + cst[a][b][4]);  // ( 0, 1)
                v = fminf(v, p[a+2][b  ] + cst[a][b][5]);  // ( 1,-1)
                v = fminf(v, p[a+2][b+1] + cst[a][b][6]);  // ( 1, 0)
                v = fminf(v, p[a+2][b+2] + cst[a][b][7]);  // ( 1, 1)
                sd[cur^1][2*ty+a+1][2*tx+b+1] = v;
            }
        cur ^= 1;
    }

    // write exact inner 32x32
    #pragma unroll
    for (int a=0;a<2;a++)
        #pragma unroll
        for (int b=0;b<2;b++){
            int r = 2*ty+a, s = 2*tx+b;
            if (r >= 8 && r < 40 && s >= 8 && s < 40){
                int gh = bh + r, gw = bw + s;
                dst[gh*WW + gw] = sd[cur][r+1][s+1];
            }
        }
}

// ---------------- final pack: heuristic + dist channels ----------------
__global__ void pack_k(float* __restrict__ out, const int* __restrict__ endn){
    int px = blockIdx.x*256 + threadIdx.x;
    int e = endn[0]*WW + endn[1];
    float om = g_omega[px];
    float varEnd = g_var[e];
    float hval = g_scal[0]*g_geo[px]
               + om*g_scal[1]*(varEnd - g_var[px])
               + (1.0f - om)*g_scal[2]*sqrtf(g_abs2[px]);
    out[(size_t)px*10 + 0] = fmaxf(hval, 0.0f);
    out[(size_t)px*10 + 9] = fminf(g_dist[0][px], BIGF);
}

// ---------------- launch ----------------
extern "C" void kernel_launch(void* const* d_in, const int* in_sizes, int n_in,
                              void* d_out, int out_size){
    const float* f = (const float*)d_in[0];
    float* out = (float*)d_out;

    cudaMemcpyToSymbolAsync(cw1,  d_in[4], CC*32*sizeof(float), 0, cudaMemcpyDeviceToDevice, 0);
    cudaMemcpyToSymbolAsync(cb1,  d_in[5], 32*sizeof(float),    0, cudaMemcpyDeviceToDevice, 0);
    cudaMemcpyToSymbolAsync(cw2,  d_in[6], 32*sizeof(float),    0, cudaMemcpyDeviceToDevice, 0);
    cudaMemcpyToSymbolAsync(cb2v, d_in[7], sizeof(float),       0, cudaMemcpyDeviceToDevice, 0);

    k0<<<1,64>>>(f, (const float*)d_in[1], (const float*)d_in[2],
                 (const float*)d_in[3], (const int*)d_in[9]);
    cost_k<<<(HH*WW)/8, 256>>>(f, out);
    heur_tile<<<dim3(16,16), 256>>>(f);
    mlp_k<<<256, 256>>>(f);
    dist_init<<<256, 256>>>((const int*)d_in[8]);
    for (int k = 0; k < 32; k++)
        dist_relax<<<dim3(8,8), 576>>>(k & 1);
    pack_k<<<256, 256>>>(out, (const int*)d_in[9]);
}

// round 2
// speedup vs baseline: 1.2485x; 1.2485x over previous
#include <cuda_runtime.h>
#include <math.h>

#define HH 256
#define WW 256
#define CC 128
#define BIGF 1000000000.0f

// ---------------- device scratch (static, no allocation) ----------------
__device__ float g_cost[HH*WW*8];     // cost[p][dir]
__device__ float g_dist[2][HH*WW];    // ping-pong distance buffers
__device__ float g_geo [HH*WW];
__device__ float g_var [HH*WW];
__device__ float g_abs2[HH*WW];
__device__ float g_omega[HH*WW];
__device__ float g_endlf[64];
__device__ float g_scal[3];           // softplus(delta, gamma, beta)
__device__ unsigned g_arrive;         // persistent-kernel barrier counter

__device__ __forceinline__ float softplusf(float x){
    return x > 30.0f ? x : log1pf(expf(x));
}

// ---------------- kernel 0: scalars + end-pixel lo-freq features ----------------
__global__ void k0(const float* __restrict__ f, const float* dl, const float* gm,
                   const float* bt, const int* __restrict__ endn){
    int t = threadIdx.x;
    if (t == 0){
        g_scal[0] = softplusf(*dl);
        g_scal[1] = softplusf(*gm);
        g_scal[2] = softplusf(*bt);
    }
    int e = endn[0]*WW + endn[1];
    if (t < 64) g_endlf[t] = f[(size_t)e*CC + t];
}

// ---------------- cost grid: SMEM-tiled, symmetric-pair (4 dirs computed) ------
// DIRS order: 0:(-1,-1) 1:(-1,0) 2:(-1,1) 3:(0,-1) 4:(0,1) 5:(1,-1) 6:(1,0) 7:(1,1)
// cost[p][i] == cost[p+d_i][7-i]; we compute i=4..7 and mirror-write.
__global__ void cost_k2(const float* __restrict__ f, float* __restrict__ out){
    __shared__ float sfeat[306*17];   // 17 rows x 18 cols cells, 16 ch, pad 17
    __shared__ float snorm[306];
    int tid = threadIdx.x;
    int tx = tid & 15, ty = tid >> 4;
    int bh = blockIdx.y*16, bw = blockIdx.x*16;
    int own = ty*18 + tx + 1;         // region: rows 0..16 (down halo), cols -1..16

    // halo cells (50): col -1 (17), col 16 (17), row 16 cols 0..15 (16)
    int hsidx = -1; int hgh = 0, hgw = 0;
    if (tid < 17)      { hsidx = tid*18;            hgh = bh + tid;    hgw = bw - 1;  }
    else if (tid < 34) { int r = tid-17; hsidx = r*18 + 17; hgh = bh + r; hgw = bw + 16; }
    else if (tid < 50) { int c = tid-34; hsidx = 289 + c;   hgh = bh + 16; hgw = bw + c; }

    float dot4[4] = {0.f,0.f,0.f,0.f};
    float ownss = 0.0f, hss = 0.0f;
    const int nbo[4] = {1, 17, 18, 19};   // (0,1),(1,-1),(1,0),(1,1) in cell space

    for (int ck = 0; ck < 8; ck++){
        int c0 = ck*16;
        __syncthreads();
        for (int idx = tid; idx < 1224; idx += 256){
            int cell = idx >> 2, q = idx & 3;
            int r = cell / 18, cc = cell % 18;
            int gh = bh + r, gw = bw + cc - 1;
            float4 v = make_float4(0.f,0.f,0.f,0.f);
            if ((unsigned)gh < HH && (unsigned)gw < WW)
                v = *(const float4*)(f + (size_t)(gh*WW+gw)*CC + c0 + q*4);
            float* sp = sfeat + cell*17 + q*4;
            sp[0]=v.x; sp[1]=v.y; sp[2]=v.z; sp[3]=v.w;
        }
        __syncthreads();

        float a[16];
        #pragma unroll
        for (int ch=0; ch<16; ch++){
            a[ch] = sfeat[own*17 + ch];
            ownss = fmaf(a[ch], a[ch], ownss);
        }
        #pragma unroll
        for (int d=0; d<4; d++){
            const float* nb = sfeat + (own + nbo[d])*17;
            float s = 0.f;
            #pragma unroll
            for (int ch=0; ch<16; ch++) s = fmaf(a[ch], nb[ch], s);
            dot4[d] += s;
        }
        if (tid < 50){
            const float* hb = sfeat + hsidx*17;
            #pragma unroll
            for (int ch=0; ch<16; ch++) hss = fmaf(hb[ch], hb[ch], hss);
        }
    }
    __syncthreads();
    snorm[own] = ownss;
    if (tid < 50) snorm[hsidx] = hss;
    __syncthreads();

    int h = bh + ty, w = bw + tx;
    int px = h*WW + w;
    float invp = 1.0f / fmaxf(sqrtf(ownss), 1e-12f);

    const int ddx[4] = {0,1,1,1};
    const int ddy[4] = {1,-1,0,1};
    #pragma unroll
    for (int d=0; d<4; d++){
        int i = 4 + d;
        int nh = h + ddx[d], nw = w + ddy[d];
        if ((unsigned)nh < HH && (unsigned)nw < WW){
            float nn = snorm[own + nbo[d]];
            float val = 1.0f - dot4[d] * invp / fmaxf(sqrtf(nn), 1e-12f);
            int npx = nh*WW + nw;
            g_cost[(size_t)px *8 + i]      = val;
            out   [(size_t)px *10 + 1 + i] = val;
            g_cost[(size_t)npx*8 + (7-i)]      = val;
            out   [(size_t)npx*10 + 1 + (7-i)] = val;
        } else {
            g_cost[(size_t)px*8 + i]      = BIGF;
            out   [(size_t)px*10 + 1 + i] = BIGF;
        }
    }
    // dirs 0..3 whose pair-owner is out of grid -> BIG (written by self)
    const int udx[4] = {-1,-1,-1, 0};
    const int udy[4] = {-1, 0, 1,-1};
    #pragma unroll
    for (int j=0; j<4; j++){
        int nh = h + udx[j], nw = w + udy[j];
        if (!((unsigned)nh < HH && (unsigned)nw < WW)){
            g_cost[(size_t)px*8 + j]      = BIGF;
            out   [(size_t)px*10 + 1 + j] = BIGF;
        }
    }
}

// ---------------- heuristic tile: sobel + var(3x3) + absorption ----------------
__global__ void heur_tile(const float* __restrict__ f){
    __shared__ float s[324*17];             // 18x18 cells x 16 channels, pad 17
    int tid = threadIdx.x;
    int tx = tid & 15, ty = tid >> 4;
    int bh = blockIdx.y*16, bw = blockIdx.x*16;

    float geo = 0.0f, var = 0.0f, ab2 = 0.0f;

    for (int ck = 0; ck < 8; ck++){
        int c0 = ck*16;
        __syncthreads();
        for (int idx = tid; idx < 1296; idx += 256){
            int cell = idx >> 2, q = idx & 3;
            int r = cell / 18, col = cell % 18;
            int gh = bh + r - 1, gw = bw + col - 1;
            float4 v = make_float4(0.f,0.f,0.f,0.f);
            if ((unsigned)gh < HH && (unsigned)gw < WW)
                v = *(const float4*)(f + (size_t)(gh*WW+gw)*CC + c0 + q*4);
            float* sp = s + cell*17 + q*4;
            sp[0]=v.x; sp[1]=v.y; sp[2]=v.z; sp[3]=v.w;
        }
        __syncthreads();

        int base = (ty+1)*18 + (tx+1);
        #pragma unroll
        for (int ch = 0; ch < 16; ch++){
            float v00 = s[(base-19)*17+ch], v01 = s[(base-18)*17+ch], v02 = s[(base-17)*17+ch];
            float v10 = s[(base- 1)*17+ch], v11 = s[(base   )*17+ch], v12 = s[(base+ 1)*17+ch];
            float v20 = s[(base+17)*17+ch], v21 = s[(base+18)*17+ch], v22 = s[(base+19)*17+ch];
            float gx = (v02 - v00) + 2.0f*(v12 - v10) + (v22 - v20);
            float gy = (v20 - v00) + 2.0f*(v21 - v01) + (v22 - v02);
            geo += sqrtf(gx*gx + gy*gy);
            int c = c0 + ch;
            if (c >= 64){
                float xs = v00+v01+v02+v10+v11+v12+v20+v21+v22;
                float x2 = v00*v00+v01*v01+v02*v02+v10*v10+v11*v11+v12*v12+v20*v20+v21*v21+v22*v22;
                float m1 = xs * (1.0f/9.0f);
                var += x2 * (1.0f/9.0f) - m1*m1;
            } else {
                float d = v11 - g_endlf[c];
                ab2 += d*d;
            }
        }
    }
    int px = (bh+ty)*WW + (bw+tx);
    g_geo [px] = geo * (1.0f/128.0f);
    g_var [px] = var;
    g_abs2[px] = ab2;
}

// ---------------- MLP: W1 in SMEM (broadcast LDS.128), thread per pixel --------
__global__ void mlp_k(const float* __restrict__ f, const float* __restrict__ w1,
                      const float* __restrict__ b1, const float* __restrict__ w2,
                      const float* __restrict__ b2){
    __shared__ __align__(16) float sw[CC*32];        // 16 KB
    __shared__ float sf[256*17];                     // 256 px x 16 ch, pad 17
    int tid = threadIdx.x;
    int pxbase = blockIdx.x*256;

    for (int i = tid; i < 1024; i += 256)
        *(float4*)(sw + i*4) = *(const float4*)(w1 + i*4);

    float acc[32];
    #pragma unroll
    for (int j=0;j<32;j++) acc[j] = b1[j];

    for (int ck = 0; ck < 8; ck++){
        int c0 = ck*16;
        __syncthreads();
        for (int idx = tid; idx < 1024; idx += 256){
            int p = idx >> 2, q = idx & 3;
            float4 v = *(const float4*)(f + (size_t)(pxbase+p)*CC + c0 + q*4);
            float* sp = sf + p*17 + q*4;
            sp[0]=v.x; sp[1]=v.y; sp[2]=v.z; sp[3]=v.w;
        }
        __syncthreads();
        #pragma unroll
        for (int c = 0; c < 16; c++){
            float fc = sf[tid*17 + c];
            const float4* wr = (const float4*)(sw + (c0 + c)*32);
            #pragma unroll
            for (int q = 0; q < 8; q++){
                float4 wv = wr[q];
                acc[q*4+0] = fmaf(fc, wv.x, acc[q*4+0]);
                acc[q*4+1] = fmaf(fc, wv.y, acc[q*4+1]);
                acc[q*4+2] = fmaf(fc, wv.z, acc[q*4+2]);
                acc[q*4+3] = fmaf(fc, wv.w, acc[q*4+3]);
            }
        }
    }
    float z = b2[0];
    #pragma unroll
    for (int j=0;j<32;j++) z = fmaf(fmaxf(acc[j], 0.0f), w2[j], z);
    g_omega[pxbase + tid] = 1.0f / (1.0f + expf(-z));
}

// ---------------- distance init (also resets persistent barrier) ----------------
__global__ void dist_init(const int* __restrict__ startn){
    int idx = blockIdx.x*256 + threadIdx.x;
    int s = startn[0]*WW + startn[1];
    g_dist[0][idx] = (idx == s) ? 0.0f : BIGF;
    if (idx == 0) g_arrive = 0u;
}

// ---------------- persistent relaxation: 32 phases x K=8 fused iterations ------
// grid 11x11 = 121 blocks (< 148 SMs -> all co-resident), 400 threads.
// Output tile 24x24, region 40x40 (halo 8). Costs live in registers for the
// whole kernel. Global sync between phases via monotonic atomic counter.
__global__ void __launch_bounds__(400,1) dist_relax_persist(){
    __shared__ __align__(16) float sd[2][42][44];
    int tid = threadIdx.x;
    int tx = tid % 20, ty = tid / 20;
    int bh = blockIdx.y*24 - 8, bw = blockIdx.x*24 - 8;
    const unsigned NBLK = 121u;

    // BIG ring (both buffers), once; never rewritten by iterations
    for (int idx = tid; idx < 2*42*44; idx += 400){
        int l = idx / (42*44);
        int rem = idx % (42*44);
        int r = rem / 44, c = rem % 44;
        if (r == 0 || r == 41 || c == 0 || c >= 41)
            sd[l][r][c] = BIGF;
    }

    // own-cell costs in registers: cost[p][j] pairs with neighbor p + d_j
    float cst[2][2][8];
    #pragma unroll
    for (int a=0;a<2;a++)
    #pragma unroll
    for (int b=0;b<2;b++){
        int gh = bh + 2*ty + a, gw = bw + 2*tx + b;
        if ((unsigned)gh < HH && (unsigned)gw < WW){
            const float4* cp = (const float4*)(g_cost + (size_t)(gh*WW+gw)*8);
            float4 u = __ldg(cp), w = __ldg(cp+1);
            cst[a][b][0]=u.x; cst[a][b][1]=u.y; cst[a][b][2]=u.z; cst[a][b][3]=u.w;
            cst[a][b][4]=w.x; cst[a][b][5]=w.y; cst[a][b][6]=w.z; cst[a][b][7]=w.w;
        } else {
            #pragma unroll
            for (int i=0;i<8;i++) cst[a][b][i] = BIGF;
        }
    }

    #pragma unroll 1
    for (int p = 0; p < 32; p++){
        const float* __restrict__ src = g_dist[p & 1];
        float*       __restrict__ dst = g_dist[(p+1) & 1];

        // load 40x40 region (L2-coherent)
        for (int idx = tid; idx < 1600; idx += 400){
            int r = idx / 40, c = idx % 40;
            int gh = bh + r, gw = bw + c;
            float v = BIGF;
            if ((unsigned)gh < HH && (unsigned)gw < WW)
                v = __ldcg(src + gh*WW + gw);
            sd[0][r+1][c+1] = v;
        }
        __syncthreads();

        int cur = 0;
        #pragma unroll 1
        for (int it = 0; it < 8; it++){
            float pp[4][4];
            #pragma unroll
            for (int i=0;i<4;i++){
                const float2* row = (const float2*)&sd[cur][2*ty+i][2*tx];
                float2 u0 = row[0], u1 = row[1];
                pp[i][0]=u0.x; pp[i][1]=u0.y; pp[i][2]=u1.x; pp[i][3]=u1.y;
            }
            #pragma unroll
            for (int a=0;a<2;a++)
                #pragma unroll
                for (int b=0;b<2;b++){
                    float v = pp[a+1][b+1];
                    v = fminf(v, pp[a  ][b  ] + cst[a][b][0]);  // (-1,-1)
                    v = fminf(v, pp[a  ][b+1] + cst[a][b][1]);  // (-1, 0)
                    v = fminf(v, pp[a  ][b+2] + cst[a][b][2]);  // (-1, 1)
                    v = fminf(v, pp[a+1][b  ] + cst[a][b][3]);  // ( 0,-1)
                    v = fminf(v, pp[a+1][b+2] + cst[a][b][4]);  // ( 0, 1)
                    v = fminf(v, pp[a+2][b  ] + cst[a][b][5]);  // ( 1,-1)
                    v = fminf(v, pp[a+2][b+1] + cst[a][b][6]);  // ( 1, 0)
                    v = fminf(v, pp[a+2][b+2] + cst[a][b][7]);  // ( 1, 1)
                    sd[cur^1][2*ty+a+1][2*tx+b+1] = v;
                }
            cur ^= 1;
            __syncthreads();
        }
        // after 8 iterations (even), final data sits in sd[0]

        // write exact inner 24x24 (region coords [8,32))
        #pragma unroll
        for (int a=0;a<2;a++)
            #pragma unroll
            for (int b=0;b<2;b++){
                int r = 2*ty+a, c = 2*tx+b;
                if (r >= 8 && r < 32 && c >= 8 && c < 32){
                    int gh = bh + r, gw = bw + c;
                    if (gh < HH && gw < WW)
                        __stcg(dst + gh*WW + gw, sd[0][r+1][c+1]);
                }
            }

        // global phase barrier
        __threadfence();
        __syncthreads();
        if (tid == 0){
            atomicAdd(&g_arrive, 1u);
            unsigned target = NBLK * (unsigned)(p + 1);
            while (*((volatile unsigned*)&g_arrive) < target) __nanosleep(64);
        }
        __syncthreads();
    }
}

// ---------------- final pack: heuristic + dist channels ----------------
__global__ void pack_k(float* __restrict__ out, const int* __restrict__ endn){
    int px = blockIdx.x*256 + threadIdx.x;
    int e = endn[0]*WW + endn[1];
    float om = g_omega[px];
    float varEnd = g_var[e];
    float hval = g_scal[0]*g_geo[px]
               + om*g_scal[1]*(varEnd - g_var[px])
               + (1.0f - om)*g_scal[2]*sqrtf(g_abs2[px]);
    out[(size_t)px*10 + 0] = fmaxf(hval, 0.0f);
    out[(size_t)px*10 + 9] = fminf(g_dist[0][px], BIGF);
}

// ---------------- launch ----------------
extern "C" void kernel_launch(void* const* d_in, const int* in_sizes, int n_in,
                              void* d_out, int out_size){
    const float* f = (const float*)d_in[0];
    float* out = (float*)d_out;

    k0<<<1,64>>>(f, (const float*)d_in[1], (const float*)d_in[2],
                 (const float*)d_in[3], (const int*)d_in[9]);
    cost_k2<<<dim3(16,16), 256>>>(f, out);
    heur_tile<<<dim3(16,16), 256>>>(f);
    mlp_k<<<256, 256>>>(f, (const float*)d_in[4], (const float*)d_in[5],
                        (const float*)d_in[6], (const float*)d_in[7]);
    dist_init<<<256, 256>>>((const int*)d_in[8]);
    dist_relax_persist<<<dim3(11,11), 400>>>();
    pack_k<<<256, 256>>>(out, (const int*)d_in[9]);
}

// round 4
// speedup vs baseline: 1.3376x; 1.0714x over previous
#include <cuda_runtime.h>
#include <math.h>

#define HH 256
#define WW 256
#define CC 128
#define BIGF 1000000000.0f

// ---------------- device scratch ----------------
__device__ float g_cost[HH*WW*8];
__device__ float g_dist[2][HH*WW];
__device__ float g_geo [HH*WW];
__device__ float g_var [HH*WW];
__device__ float g_abs2[HH*WW];
__device__ float g_omega[HH*WW];
__device__ float g_endlf[64];
__device__ float g_scal[3];
__device__ unsigned g_arrive;

__device__ __forceinline__ float softplusf(float x){
    return x > 30.0f ? x : log1pf(expf(x));
}

// ---------------- kernel 0 ----------------
__global__ void k0(const float* __restrict__ f, const float* dl, const float* gm,
                   const float* bt, const int* __restrict__ endn){
    int t = threadIdx.x;
    if (t == 0){
        g_scal[0] = softplusf(*dl);
        g_scal[1] = softplusf(*gm);
        g_scal[2] = softplusf(*bt);
    }
    int e = endn[0]*WW + endn[1];
    if (t < 64) g_endlf[t] = f[(size_t)e*CC + t];
}

// ---------------- fused heuristic + cost: one pass over features ----------------
// 18x18 halo tile per 16x16 output. Sobel regs double as cost-dot operands.
// DIRS: 0:(-1,-1) 1:(-1,0) 2:(-1,1) 3:(0,-1) 4:(0,1) 5:(1,-1) 6:(1,0) 7:(1,1)
// cost[p][i] == cost[p+d_i][7-i]; compute i=4..7, mirror-write.
// Edge cells needing norms (49): col0 rows2..17, col17 rows1..17, row17 cols1..16.
__global__ void hc_k(const float* __restrict__ f, float* __restrict__ out){
    __shared__ float s[324*17];          // 18x18 cells x 16 ch, pad 17
    __shared__ float snorm[324];
    int tid = threadIdx.x;
    int tx = tid & 15, ty = tid >> 4;
    int bh = blockIdx.y*16, bw = blockIdx.x*16;
    int base = (ty+1)*18 + (tx+1);       // own cell; cell (r,c) <-> (bh+r-1, bw+c-1)

    int eidx = -1;
    if (tid < 16)      eidx = (tid+2)*18;            // col 0, rows 2..17
    else if (tid < 33) eidx = (tid-15)*18 + 17;      // col 17, rows 1..17
    else if (tid < 49) eidx = 17*18 + (tid-32);      // row 17, cols 1..16

    float geo = 0.0f, var = 0.0f, ab2 = 0.0f;
    float dot4[4] = {0.f,0.f,0.f,0.f};
    float ownss = 0.0f, ess = 0.0f;

    for (int ck = 0; ck < 8; ck++){
        int c0 = ck*16;
        __syncthreads();
        for (int idx = tid; idx < 1296; idx += 256){
            int cell = idx >> 2, q = idx & 3;
            int r = cell / 18, col = cell % 18;
            int gh = bh + r - 1, gw = bw + col - 1;
            float4 v = make_float4(0.f,0.f,0.f,0.f);
            if ((unsigned)gh < HH && (unsigned)gw < WW)
                v = *(const float4*)(f + (size_t)(gh*WW+gw)*CC + c0 + q*4);
            float* sp = s + cell*17 + q*4;
            sp[0]=v.x; sp[1]=v.y; sp[2]=v.z; sp[3]=v.w;
        }
        __syncthreads();

        #pragma unroll
        for (int ch = 0; ch < 16; ch++){
            float v00 = s[(base-19)*17+ch], v01 = s[(base-18)*17+ch], v02 = s[(base-17)*17+ch];
            float v10 = s[(base- 1)*17+ch], v11 = s[(base   )*17+ch], v12 = s[(base+ 1)*17+ch];
            float v20 = s[(base+17)*17+ch], v21 = s[(base+18)*17+ch], v22 = s[(base+19)*17+ch];
            float gx = (v02 - v00) + 2.0f*(v12 - v10) + (v22 - v20);
            float gy = (v20 - v00) + 2.0f*(v21 - v01) + (v22 - v02);
            geo += sqrtf(gx*gx + gy*gy);
            // cost dots ride free on loaded regs
            ownss  = fmaf(v11, v11, ownss);
            dot4[0] = fmaf(v11, v12, dot4[0]);   // (0, 1)
            dot4[1] = fmaf(v11, v20, dot4[1]);   // (1,-1)
            dot4[2] = fmaf(v11, v21, dot4[2]);   // (1, 0)
            dot4[3] = fmaf(v11, v22, dot4[3]);   // (1, 1)
            int c = c0 + ch;
            if (c >= 64){
                float xs = v00+v01+v02+v10+v11+v12+v20+v21+v22;
                float x2 = v00*v00+v01*v01+v02*v02+v10*v10+v11*v11+v12*v12+v20*v20+v21*v21+v22*v22;
                float m1 = xs * (1.0f/9.0f);
                var += x2 * (1.0f/9.0f) - m1*m1;
            } else {
                float d = v11 - g_endlf[c];
                ab2 += d*d;
            }
        }
        if (tid < 49){
            const float* eb = s + eidx*17;
            #pragma unroll
            for (int ch=0; ch<16; ch++) ess = fmaf(eb[ch], eb[ch], ess);
        }
    }

    int px = (bh+ty)*WW + (bw+tx);
    g_geo [px] = geo * (1.0f/128.0f);
    g_var [px] = var;
    g_abs2[px] = ab2;

    __syncthreads();
    snorm[base] = ownss;
    if (tid < 49) snorm[eidx] = ess;
    __syncthreads();

    int h = bh + ty, w = bw + tx;
    float invp = 1.0f / fmaxf(sqrtf(ownss), 1e-12f);
    const int nbo[4] = {1, 17, 18, 19};
    const int ddx[4] = {0,1,1,1};
    const int ddy[4] = {1,-1,0,1};
    #pragma unroll
    for (int d=0; d<4; d++){
        int i = 4 + d;
        int nh = h + ddx[d], nw = w + ddy[d];
        if ((unsigned)nh < HH && (unsigned)nw < WW){
            float nn = snorm[base + nbo[d]];
            float val = 1.0f - dot4[d] * invp / fmaxf(sqrtf(nn), 1e-12f);
            int npx = nh*WW + nw;
            g_cost[(size_t)px *8 + i]          = val;
            out   [(size_t)px *10 + 1 + i]     = val;
            g_cost[(size_t)npx*8 + (7-i)]      = val;
            out   [(size_t)npx*10 + 1 + (7-i)] = val;
        } else {
            g_cost[(size_t)px*8 + i]      = BIGF;
            out   [(size_t)px*10 + 1 + i] = BIGF;
        }
    }
    const int udx[4] = {-1,-1,-1, 0};
    const int udy[4] = {-1, 0, 1,-1};
    #pragma unroll
    for (int j=0; j<4; j++){
        int nh = h + udx[j], nw = w + udy[j];
        if (!((unsigned)nh < HH && (unsigned)nw < WW)){
            g_cost[(size_t)px*8 + j]      = BIGF;
            out   [(size_t)px*10 + 1 + j] = BIGF;
        }
    }
}

// ---------------- MLP: 2 pixels/thread, W1 in SMEM ----------------
__global__ void mlp_k(const float* __restrict__ f, const float* __restrict__ w1,
                      const float* __restrict__ b1, const float* __restrict__ w2,
                      const float* __restrict__ b2){
    __shared__ __align__(16) float sw[CC*32];    // 16 KB
    __shared__ float sf[512*9];                  // 512 px x 8 ch, pad 9
    int tid = threadIdx.x;
    int pxbase = blockIdx.x*512;

    for (int i = tid; i < 1024; i += 256)
        *(float4*)(sw + i*4) = *(const float4*)(w1 + i*4);

    float acc0[32], acc1[32];
    #pragma unroll
    for (int j=0;j<32;j++){ float b = b1[j]; acc0[j] = b; acc1[j] = b; }

    for (int ck = 0; ck < 16; ck++){
        int c0 = ck*8;
        __syncthreads();
        for (int idx = tid; idx < 1024; idx += 256){
            int p = idx >> 1, q = idx & 1;
            float4 v = *(const float4*)(f + (size_t)(pxbase+p)*CC + c0 + q*4);
            float* sp = sf + p*9 + q*4;
            sp[0]=v.x; sp[1]=v.y; sp[2]=v.z; sp[3]=v.w;
        }
        __syncthreads();
        #pragma unroll
        for (int c = 0; c < 8; c++){
            float fa = sf[tid*9 + c];
            float fb = sf[(tid+256)*9 + c];
            const float4* wr = (const float4*)(sw + (c0 + c)*32);
            #pragma unroll
            for (int q = 0; q < 8; q++){
                float4 wv = wr[q];
                acc0[q*4+0] = fmaf(fa, wv.x, acc0[q*4+0]);
                acc0[q*4+1] = fmaf(fa, wv.y, acc0[q*4+1]);
                acc0[q*4+2] = fmaf(fa, wv.z, acc0[q*4+2]);
                acc0[q*4+3] = fmaf(fa, wv.w, acc0[q*4+3]);
                acc1[q*4+0] = fmaf(fb, wv.x, acc1[q*4+0]);
                acc1[q*4+1] = fmaf(fb, wv.y, acc1[q*4+1]);
                acc1[q*4+2] = fmaf(fb, wv.z, acc1[q*4+2]);
                acc1[q*4+3] = fmaf(fb, wv.w, acc1[q*4+3]);
            }
        }
    }
    float w2r, z0 = b2[0], z1 = z0;
    #pragma unroll
    for (int j=0;j<32;j++){
        w2r = w2[j];
        z0 = fmaf(fmaxf(acc0[j], 0.0f), w2r, z0);
        z1 = fmaf(fmaxf(acc1[j], 0.0f), w2r, z1);
    }
    g_omega[pxbase + tid]       = 1.0f / (1.0f + expf(-z0));
    g_omega[pxbase + tid + 256] = 1.0f / (1.0f + expf(-z1));
}

// ---------------- distance init ----------------
__global__ void dist_init(const int* __restrict__ startn){
    int idx = blockIdx.x*256 + threadIdx.x;
    int s = startn[0]*WW + startn[1];
    g_dist[0][idx] = (idx == s) ? 0.0f : BIGF;
    if (idx == 0) g_arrive = 0u;
}

// ---------------- persistent relaxation: 800 threads, 2 cells/thread ----------
// 121 blocks (co-resident), 24x24 tile + 8 halo = 40x40 region, 32 phases x 8 iters.
__global__ void __launch_bounds__(800,1) dist_relax_persist(){
    __shared__ __align__(16) float sd[2][42][44];
    int tid = threadIdx.x;
    int tx = tid % 20, ty = tid / 20;     // ty 0..39 region row, cols 2tx,2tx+1
    int bh = blockIdx.y*24 - 8, bw = blockIdx.x*24 - 8;
    const unsigned NBLK = 121u;

    // BIG ring once (rows 0,41; cols 0,41..43)
    for (int idx = tid; idx < 2*42*44; idx += 800){
        int l = idx / (42*44);
        int rem = idx % (42*44);
        int r = rem / 44, c = rem % 44;
        if (r == 0 || r == 41 || c == 0 || c >= 41)
            sd[l][r][c] = BIGF;
    }

    // own-cell costs in registers (2 cells)
    float cst[2][8];
    #pragma unroll
    for (int b=0;b<2;b++){
        int gh = bh + ty, gw = bw + 2*tx + b;
        if ((unsigned)gh < HH && (unsigned)gw < WW){
            const float4* cp = (const float4*)(g_cost + (size_t)(gh*WW+gw)*8);
            float4 u = __ldg(cp), w = __ldg(cp+1);
            cst[b][0]=u.x; cst[b][1]=u.y; cst[b][2]=u.z; cst[b][3]=u.w;
            cst[b][4]=w.x; cst[b][5]=w.y; cst[b][6]=w.z; cst[b][7]=w.w;
        } else {
            #pragma unroll
            for (int i=0;i<8;i++) cst[b][i] = BIGF;
        }
    }

    #pragma unroll 1
    for (int p = 0; p < 32; p++){
        const float* __restrict__ src = g_dist[p & 1];
        float*       __restrict__ dst = g_dist[(p+1) & 1];

        for (int idx = tid; idx < 1600; idx += 800){
            int r = idx / 40, c = idx % 40;
            int gh = bh + r, gw = bw + c;
            float v = BIGF;
            if ((unsigned)gh < HH && (unsigned)gw < WW)
                v = __ldcg(src + gh*WW + gw);
            sd[0][r+1][c+1] = v;
        }
        __syncthreads();

        int cur = 0;
        #pragma unroll 1
        for (int it = 0; it < 8; it++){
            float p00 = sd[cur][ty  ][2*tx  ], p01 = sd[cur][ty  ][2*tx+1];
            float p02 = sd[cur][ty  ][2*tx+2], p03 = sd[cur][ty  ][2*tx+3];
            float p10 = sd[cur][ty+1][2*tx  ], p11 = sd[cur][ty+1][2*tx+1];
            float p12 = sd[cur][ty+1][2*tx+2], p13 = sd[cur][ty+1][2*tx+3];
            float p20 = sd[cur][ty+2][2*tx  ], p21 = sd[cur][ty+2][2*tx+1];
            float p22 = sd[cur][ty+2][2*tx+2], p23 = sd[cur][ty+2][2*tx+3];

            float v0 = p11;
            v0 = fminf(v0, p00 + cst[0][0]);
            v0 = fminf(v0, p01 + cst[0][1]);
            v0 = fminf(v0, p02 + cst[0][2]);
            v0 = fminf(v0, p10 + cst[0][3]);
            v0 = fminf(v0, p12 + cst[0][4]);
            v0 = fminf(v0, p20 + cst[0][5]);
            v0 = fminf(v0, p21 + cst[0][6]);
            v0 = fminf(v0, p22 + cst[0][7]);

            float v1 = p12;
            v1 = fminf(v1, p01 + cst[1][0]);
            v1 = fminf(v1, p02 + cst[1][1]);
            v1 = fminf(v1, p03 + cst[1][2]);
            v1 = fminf(v1, p11 + cst[1][3]);
            v1 = fminf(v1, p13 + cst[1][4]);
            v1 = fminf(v1, p21 + cst[1][5]);
            v1 = fminf(v1, p22 + cst[1][6]);
            v1 = fminf(v1, p23 + cst[1][7]);

            sd[cur^1][ty+1][2*tx+1] = v0;
            sd[cur^1][ty+1][2*tx+2] = v1;
            cur ^= 1;
            __syncthreads();
        }
        // 8 iterations (even) -> result in sd[0]

        // exact inner 24x24: rows 8..31, cols 8..31
        if (ty >= 8 && ty < 32 && tx >= 4 && tx < 16){
            int gh = bh + ty, gw = bw + 2*tx;
            if (gh < HH && gw < WW){
                __stcg(dst + gh*WW + gw,     sd[0][ty+1][2*tx+1]);
                __stcg(dst + gh*WW + gw + 1, sd[0][ty+1][2*tx+2]);
            }
        }

        __threadfence();
        __syncthreads();
        if (tid == 0){
            atomicAdd(&g_arrive, 1u);
            unsigned target = NBLK * (unsigned)(p + 1);
            while (*((volatile unsigned*)&g_arrive) < target) __nanosleep(64);
        }
        __syncthreads();
    }
}

// ---------------- final pack ----------------
__global__ void pack_k(float* __restrict__ out, const int* __restrict__ endn){
    int px = blockIdx.x*256 + threadIdx.x;
    int e = endn[0]*WW + endn[1];
    float om = g_omega[px];
    float varEnd = g_var[e];
    float hval = g_scal[0]*g_geo[px]
               + om*g_scal[1]*(varEnd - g_var[px])
               + (1.0f - om)*g_scal[2]*sqrtf(g_abs2[px]);
    out[(size_t)px*10 + 0] = fmaxf(hval, 0.0f);
    out[(size_t)px*10 + 9] = fminf(g_dist[0][px], BIGF);
}

// ---------------- launch ----------------
extern "C" void kernel_launch(void* const* d_in, const int* in_sizes, int n_in,
                              void* d_out, int out_size){
    const float* f = (const float*)d_in[0];
    float* out = (float*)d_out;

    k0<<<1,64>>>(f, (const float*)d_in[1], (const float*)d_in[2],
                 (const float*)d_in[3], (const int*)d_in[9]);
    hc_k<<<dim3(16,16), 256>>>(f, out);
    mlp_k<<<128, 256>>>(f, (const float*)d_in[4], (const float*)d_in[5],
                        (const float*)d_in[6], (const float*)d_in[7]);
    dist_init<<<256, 256>>>((const int*)d_in[8]);
    dist_relax_persist<<<dim3(11,11), 800>>>();
    pack_k<<<256, 256>>>(out, (const int*)d_in[9]);
}

// round 5
// speedup vs baseline: 1.4344x; 1.0723x over previous
#include <cuda_runtime.h>
#include <math.h>

#define HH 256
#define WW 256
#define CC 128
#define BIGF 1000000000.0f

// ---------------- device scratch ----------------
__device__ float g_cost[HH*WW*8];
__device__ float g_dist[2][HH*WW];
__device__ float g_geo [HH*WW];
__device__ float g_var [HH*WW];
__device__ float g_abs2[HH*WW];
__device__ float g_omega[HH*WW];
__device__ float g_endlf[64];
__device__ float g_scal[3];
__device__ unsigned g_arrive;

__device__ __forceinline__ float softplusf(float x){
    return x > 30.0f ? x : log1pf(expf(x));
}

// packed f32x2 helpers (Blackwell)
__device__ __forceinline__ unsigned long long pk2(float x, float y){
    unsigned long long r;
    asm("mov.b64 %0, {%1, %2};" : "=l"(r) : "f"(x), "f"(y));
    return r;
}
__device__ __forceinline__ void fma2(unsigned long long &d, unsigned long long a,
                                     unsigned long long b){
    asm("fma.rn.f32x2 %0, %1, %2, %0;" : "+l"(d) : "l"(a), "l"(b));
}
__device__ __forceinline__ float2 upk2(unsigned long long v){
    float2 r;
    asm("mov.b64 {%0, %1}, %2;" : "=f"(r.x), "=f"(r.y) : "l"(v));
    return r;
}

// ---------------- kernel 0 ----------------
__global__ void k0(const float* __restrict__ f, const float* dl, const float* gm,
                   const float* bt, const int* __restrict__ endn){
    int t = threadIdx.x;
    if (t == 0){
        g_scal[0] = softplusf(*dl);
        g_scal[1] = softplusf(*gm);
        g_scal[2] = softplusf(*bt);
        g_arrive  = 0u;
    }
    int e = endn[0]*WW + endn[1];
    if (t < 64) g_endlf[t] = f[(size_t)e*CC + t];
}

// ---------------- fused heuristic + cost ----------------
// DIRS: 0:(-1,-1) 1:(-1,0) 2:(-1,1) 3:(0,-1) 4:(0,1) 5:(1,-1) 6:(1,0) 7:(1,1)
// cost[p][i] == cost[p+d_i][7-i]; compute i=4..7, mirror-write.
// Edge cells needing norms (49): col0 rows2..17, col17 rows1..17, row17 cols1..16.
__global__ void hc_k(const float* __restrict__ f, float* __restrict__ out){
    __shared__ float s[324*17];          // 18x18 cells x 16 ch, pad 17
    __shared__ float snorm[324];
    int tid = threadIdx.x;
    int tx = tid & 15, ty = tid >> 4;
    int bh = blockIdx.y*16, bw = blockIdx.x*16;
    int base = (ty+1)*18 + (tx+1);

    int eidx = -1;
    if (tid < 16)      eidx = (tid+2)*18;            // col 0, rows 2..17
    else if (tid < 33) eidx = (tid-15)*18 + 17;      // col 17, rows 1..17
    else if (tid < 49) eidx = 17*18 + (tid-32);      // row 17, cols 1..16

    float geo = 0.0f, var = 0.0f, ab2 = 0.0f;
    float dot4[4] = {0.f,0.f,0.f,0.f};
    float ownss = 0.0f, ess = 0.0f;

    for (int ck = 0; ck < 8; ck++){
        int c0 = ck*16;
        __syncthreads();
        for (int idx = tid; idx < 1296; idx += 256){
            int cell = idx >> 2, q = idx & 3;
            int r = cell / 18, col = cell % 18;
            int gh = bh + r - 1, gw = bw + col - 1;
            float4 v = make_float4(0.f,0.f,0.f,0.f);
            if ((unsigned)gh < HH && (unsigned)gw < WW)
                v = *(const float4*)(f + (size_t)(gh*WW+gw)*CC + c0 + q*4);
            float* sp = s + cell*17 + q*4;
            sp[0]=v.x; sp[1]=v.y; sp[2]=v.z; sp[3]=v.w;
        }
        __syncthreads();

        #pragma unroll
        for (int ch = 0; ch < 16; ch++){
            float v00 = s[(base-19)*17+ch], v01 = s[(base-18)*17+ch], v02 = s[(base-17)*17+ch];
            float v10 = s[(base- 1)*17+ch], v11 = s[(base   )*17+ch], v12 = s[(base+ 1)*17+ch];
            float v20 = s[(base+17)*17+ch], v21 = s[(base+18)*17+ch], v22 = s[(base+19)*17+ch];
            float gx = (v02 - v00) + 2.0f*(v12 - v10) + (v22 - v20);
            float gy = (v20 - v00) + 2.0f*(v21 - v01) + (v22 - v02);
            geo += sqrtf(gx*gx + gy*gy);
            ownss   = fmaf(v11, v11, ownss);
            dot4[0] = fmaf(v11, v12, dot4[0]);   // (0, 1)
            dot4[1] = fmaf(v11, v20, dot4[1]);   // (1,-1)
            dot4[2] = fmaf(v11, v21, dot4[2]);   // (1, 0)
            dot4[3] = fmaf(v11, v22, dot4[3]);   // (1, 1)
            int c = c0 + ch;
            if (c >= 64){
                float xs = v00+v01+v02+v10+v11+v12+v20+v21+v22;
                float x2 = v00*v00+v01*v01+v02*v02+v10*v10+v11*v11+v12*v12+v20*v20+v21*v21+v22*v22;
                float m1 = xs * (1.0f/9.0f);
                var += x2 * (1.0f/9.0f) - m1*m1;
            } else {
                float d = v11 - g_endlf[c];
                ab2 += d*d;
            }
        }
        if (tid < 49){
            const float* eb = s + eidx*17;
            #pragma unroll
            for (int ch=0; ch<16; ch++) ess = fmaf(eb[ch], eb[ch], ess);
        }
    }

    int px = (bh+ty)*WW + (bw+tx);
    g_geo [px] = geo * (1.0f/128.0f);
    g_var [px] = var;
    g_abs2[px] = ab2;

    __syncthreads();
    snorm[base] = ownss;
    if (tid < 49) snorm[eidx] = ess;
    __syncthreads();

    int h = bh + ty, w = bw + tx;
    float invp = 1.0f / fmaxf(sqrtf(ownss), 1e-12f);
    const int nbo[4] = {1, 17, 18, 19};
    const int ddx[4] = {0,1,1,1};
    const int ddy[4] = {1,-1,0,1};
    #pragma unroll
    for (int d=0; d<4; d++){
        int i = 4 + d;
        int nh = h + ddx[d], nw = w + ddy[d];
        if ((unsigned)nh < HH && (unsigned)nw < WW){
            float nn = snorm[base + nbo[d]];
            float val = 1.0f - dot4[d] * invp / fmaxf(sqrtf(nn), 1e-12f);
            int npx = nh*WW + nw;
            g_cost[(size_t)px *8 + i]          = val;
            out   [(size_t)px *10 + 1 + i]     = val;
            g_cost[(size_t)npx*8 + (7-i)]      = val;
            out   [(size_t)npx*10 + 1 + (7-i)] = val;
        } else {
            g_cost[(size_t)px*8 + i]      = BIGF;
            out   [(size_t)px*10 + 1 + i] = BIGF;
        }
    }
    const int udx[4] = {-1,-1,-1, 0};
    const int udy[4] = {-1, 0, 1,-1};
    #pragma unroll
    for (int j=0; j<4; j++){
        int nh = h + udx[j], nw = w + udy[j];
        if (!((unsigned)nh < HH && (unsigned)nw < WW)){
            g_cost[(size_t)px*8 + j]      = BIGF;
            out   [(size_t)px*10 + 1 + j] = BIGF;
        }
    }
}

// ---------------- MLP: f32x2 packed FFMA, 2 px/thread; + dist init -------------
__global__ void mlp_k(const float* __restrict__ f, const float* __restrict__ w1,
                      const float* __restrict__ b1, const float* __restrict__ w2,
                      const float* __restrict__ b2, const int* __restrict__ startn){
    __shared__ __align__(16) float sw[CC*32];    // 16 KB
    __shared__ float sf[512*9];
    int tid = threadIdx.x;
    int pxbase = blockIdx.x*512;

    for (int i = tid; i < 1024; i += 256)
        *(float4*)(sw + i*4) = *(const float4*)(w1 + i*4);

    // fold distance init here (touches every pixel exactly once)
    {
        int s = startn[0]*WW + startn[1];
        int p0 = pxbase + tid, p1 = p0 + 256;
        g_dist[0][p0] = (p0 == s) ? 0.0f : BIGF;
        g_dist[0][p1] = (p1 == s) ? 0.0f : BIGF;
    }

    unsigned long long acc0[16], acc1[16];
    #pragma unroll
    for (int j=0;j<16;j++){
        unsigned long long b = pk2(b1[2*j], b1[2*j+1]);
        acc0[j] = b; acc1[j] = b;
    }

    for (int ck = 0; ck < 16; ck++){
        int c0 = ck*8;
        __syncthreads();
        for (int idx = tid; idx < 1024; idx += 256){
            int p = idx >> 1, q = idx & 1;
            float4 v = *(const float4*)(f + (size_t)(pxbase+p)*CC + c0 + q*4);
            float* sp = sf + p*9 + q*4;
            sp[0]=v.x; sp[1]=v.y; sp[2]=v.z; sp[3]=v.w;
        }
        __syncthreads();
        #pragma unroll
        for (int c = 0; c < 8; c++){
            float fa = sf[tid*9 + c];
            float fb = sf[(tid+256)*9 + c];
            unsigned long long fa2 = pk2(fa, fa);
            unsigned long long fb2 = pk2(fb, fb);
            const ulonglong2* wr = (const ulonglong2*)(sw + (c0 + c)*32);
            #pragma unroll
            for (int q = 0; q < 8; q++){
                ulonglong2 wv = wr[q];
                fma2(acc0[2*q  ], fa2, wv.x);
                fma2(acc0[2*q+1], fa2, wv.y);
                fma2(acc1[2*q  ], fb2, wv.x);
                fma2(acc1[2*q+1], fb2, wv.y);
            }
        }
    }
    float z0 = b2[0], z1 = z0;
    #pragma unroll
    for (int j=0;j<16;j++){
        float2 u0 = upk2(acc0[j]);
        float2 u1 = upk2(acc1[j]);
        float wa = w2[2*j], wb = w2[2*j+1];
        z0 = fmaf(fmaxf(u0.x, 0.0f), wa, z0);
        z0 = fmaf(fmaxf(u0.y, 0.0f), wb, z0);
        z1 = fmaf(fmaxf(u1.x, 0.0f), wa, z1);
        z1 = fmaf(fmaxf(u1.y, 0.0f), wb, z1);
    }
    g_omega[pxbase + tid]       = 1.0f / (1.0f + expf(-z0));
    g_omega[pxbase + tid + 256] = 1.0f / (1.0f + expf(-z1));
}

// ---------------- persistent relaxation + fused final pack ---------------------
// 121 blocks, 800 threads, 24x24 tile + 8 halo, 32 phases x 8 iters.
// Iteration k only computes the exactness cone [1+k, 38-k] (region coords).
// Last phase writes final output channels 0 and 9 directly from SMEM.
__global__ void __launch_bounds__(800,1) dist_relax_persist(const int* __restrict__ endn,
                                                            float* __restrict__ out){
    __shared__ __align__(16) float sd[2][42][44];
    int tid = threadIdx.x;
    int tx = tid % 20, ty = tid / 20;     // ty = region row 0..39; cells cols 2tx,2tx+1
    int bh = blockIdx.y*24 - 8, bw = blockIdx.x*24 - 8;
    const unsigned NBLK = 121u;

    // ring init (defensive; cone never reads it)
    for (int idx = tid; idx < 2*42*44; idx += 800){
        int l = idx / (42*44);
        int rem = idx % (42*44);
        int r = rem / 44, c = rem % 44;
        if (r == 0 || r == 41 || c == 0 || c >= 41)
            sd[l][r][c] = BIGF;
    }

    float cst[2][8];
    #pragma unroll
    for (int b=0;b<2;b++){
        int gh = bh + ty, gw = bw + 2*tx + b;
        if ((unsigned)gh < HH && (unsigned)gw < WW){
            const float4* cp = (const float4*)(g_cost + (size_t)(gh*WW+gw)*8);
            float4 u = __ldg(cp), w = __ldg(cp+1);
            cst[b][0]=u.x; cst[b][1]=u.y; cst[b][2]=u.z; cst[b][3]=u.w;
            cst[b][4]=w.x; cst[b][5]=w.y; cst[b][6]=w.z; cst[b][7]=w.w;
        } else {
            #pragma unroll
            for (int i=0;i<8;i++) cst[b][i] = BIGF;
        }
    }

    #pragma unroll 1
    for (int p = 0; p < 32; p++){
        const float* __restrict__ src = g_dist[p & 1];
        float*       __restrict__ dst = g_dist[(p+1) & 1];

        for (int idx = tid; idx < 1600; idx += 800){
            int r = idx / 40, c = idx % 40;
            int gh = bh + r, gw = bw + c;
            float v = BIGF;
            if ((unsigned)gh < HH && (unsigned)gw < WW)
                v = __ldcg(src + gh*WW + gw);
            sd[0][r+1][c+1] = v;
        }
        __syncthreads();

        int cur = 0;
        #pragma unroll 1
        for (int it = 0; it < 8; it++){
            bool act = (ty >= 1+it) && (ty <= 38-it) &&
                       (2*tx+1 >= 1+it) && (2*tx <= 38-it);
            if (act){
                float2 a0 = *(const float2*)&sd[cur][ty  ][2*tx];
                float2 a1 = *(const float2*)&sd[cur][ty  ][2*tx+2];
                float2 b0 = *(const float2*)&sd[cur][ty+1][2*tx];
                float2 b1 = *(const float2*)&sd[cur][ty+1][2*tx+2];
                float2 c0 = *(const float2*)&sd[cur][ty+2][2*tx];
                float2 c1 = *(const float2*)&sd[cur][ty+2][2*tx+2];

                float v0 = b0.y;
                v0 = fminf(v0, a0.x + cst[0][0]);
                v0 = fminf(v0, a0.y + cst[0][1]);
                v0 = fminf(v0, a1.x + cst[0][2]);
                v0 = fminf(v0, b0.x + cst[0][3]);
                v0 = fminf(v0, b1.x + cst[0][4]);
                v0 = fminf(v0, c0.x + cst[0][5]);
                v0 = fminf(v0, c0.y + cst[0][6]);
                v0 = fminf(v0, c1.x + cst[0][7]);

                float v1 = b1.x;
                v1 = fminf(v1, a0.y + cst[1][0]);
                v1 = fminf(v1, a1.x + cst[1][1]);
                v1 = fminf(v1, a1.y + cst[1][2]);
                v1 = fminf(v1, b0.y + cst[1][3]);
                v1 = fminf(v1, b1.y + cst[1][4]);
                v1 = fminf(v1, c0.y + cst[1][5]);
                v1 = fminf(v1, c1.x + cst[1][6]);
                v1 = fminf(v1, c1.y + cst[1][7]);

                sd[cur^1][ty+1][2*tx+1] = v0;
                sd[cur^1][ty+1][2*tx+2] = v1;
            }
            cur ^= 1;
            __syncthreads();
        }
        // 8 iterations (even) -> result in sd[0], exact on region rows/cols [8,31]

        if (p < 31){
            if (ty >= 8 && ty < 32 && tx >= 4 && tx < 16){
                int gh = bh + ty, gw = bw + 2*tx;
                if (gh < HH && gw < WW){
                    __stcg(dst + gh*WW + gw,     sd[0][ty+1][2*tx+1]);
                    __stcg(dst + gh*WW + gw + 1, sd[0][ty+1][2*tx+2]);
                }
            }
            __threadfence();
            __syncthreads();
            if (tid == 0){
                atomicAdd(&g_arrive, 1u);
                unsigned target = NBLK * (unsigned)(p + 1);
                while (*((volatile unsigned*)&g_arrive) < target) __nanosleep(64);
            }
            __syncthreads();
        } else {
            // final phase: write output directly (heuristic + dist)
            if (ty >= 8 && ty < 32 && tx >= 4 && tx < 16){
                int gh = bh + ty, gw = bw + 2*tx;
                if (gh < HH && gw < WW){
                    int e = endn[0]*WW + endn[1];
                    float varEnd = g_var[e];
                    float s0 = g_scal[0], s1 = g_scal[1], s2 = g_scal[2];
                    #pragma unroll
                    for (int b=0; b<2; b++){
                        int px = gh*WW + gw + b;
                        float om = g_omega[px];
                        float hv = s0*g_geo[px]
                                 + om*s1*(varEnd - g_var[px])
                                 + (1.0f - om)*s2*sqrtf(g_abs2[px]);
                        out[(size_t)px*10 + 0] = fmaxf(hv, 0.0f);
                        out[(size_t)px*10 + 9] = fminf(sd[0][ty+1][2*tx+1+b], BIGF);
                    }
                }
            }
        }
    }
}

// ---------------- launch ----------------
extern "C" void kernel_launch(void* const* d_in, const int* in_sizes, int n_in,
                              void* d_out, int out_size){
    const float* f = (const float*)d_in[0];
    float* out = (float*)d_out;

    k0<<<1,64>>>(f, (const float*)d_in[1], (const float*)d_in[2],
                 (const float*)d_in[3], (const int*)d_in[9]);
    hc_k<<<dim3(16,16), 256>>>(f, out);
    mlp_k<<<128, 256>>>(f, (const float*)d_in[4], (const float*)d_in[5],
                        (const float*)d_in[6], (const float*)d_in[7],
                        (const int*)d_in[8]);
    dist_relax_persist<<<dim3(11,11), 800>>>((const int*)d_in[9], out);
}

// round 6
// speedup vs baseline: 1.4811x; 1.0326x over previous
#include <cuda_runtime.h>
#include <math.h>

#define HH 256
#define WW 256
#define CC 128
#define BIGF 1000000000.0f

// ---------------- device scratch ----------------
__device__ float g_cost[HH*WW*8];
__device__ float g_dist[2][HH*WW];
__device__ float g_geo [HH*WW];
__device__ float g_var [HH*WW];
__device__ float g_abs2[HH*WW];
__device__ float g_omega[HH*WW];
__device__ float g_endlf[64];
__device__ float g_scal[3];
__device__ unsigned g_arrive;

__device__ __forceinline__ float softplusf(float x){
    return x > 30.0f ? x : log1pf(expf(x));
}

// packed f32x2 helpers (Blackwell)
__device__ __forceinline__ unsigned long long pk2(float x, float y){
    unsigned long long r;
    asm("mov.b64 %0, {%1, %2};" : "=l"(r) : "f"(x), "f"(y));
    return r;
}
__device__ __forceinline__ void fma2(unsigned long long &d, unsigned long long a,
                                     unsigned long long b){
    asm("fma.rn.f32x2 %0, %1, %2, %0;" : "+l"(d) : "l"(a), "l"(b));
}
__device__ __forceinline__ float2 upk2(unsigned long long v){
    float2 r;
    asm("mov.b64 {%0, %1}, %2;" : "=f"(r.x), "=f"(r.y) : "l"(v));
    return r;
}

// ---------------- kernel 0 ----------------
__global__ void k0(const float* __restrict__ f, const float* dl, const float* gm,
                   const float* bt, const int* __restrict__ endn){
    int t = threadIdx.x;
    if (t == 0){
        g_scal[0] = softplusf(*dl);
        g_scal[1] = softplusf(*gm);
        g_scal[2] = softplusf(*bt);
        g_arrive  = 0u;
    }
    int e = endn[0]*WW + endn[1];
    if (t < 64) g_endlf[t] = f[(size_t)e*CC + t];
}

// ---------------- fused heuristic + cost ----------------
// DIRS: 0:(-1,-1) 1:(-1,0) 2:(-1,1) 3:(0,-1) 4:(0,1) 5:(1,-1) 6:(1,0) 7:(1,1)
// cost[p][i] == cost[p+d_i][7-i]; compute i=4..7, mirror-write.
__global__ void hc_k(const float* __restrict__ f, float* __restrict__ out){
    __shared__ float s[324*17];          // 18x18 cells x 16 ch, pad 17
    __shared__ float snorm[324];
    int tid = threadIdx.x;
    int tx = tid & 15, ty = tid >> 4;
    int bh = blockIdx.y*16, bw = blockIdx.x*16;
    int base = (ty+1)*18 + (tx+1);

    int eidx = -1;
    if (tid < 16)      eidx = (tid+2)*18;            // col 0, rows 2..17
    else if (tid < 33) eidx = (tid-15)*18 + 17;      // col 17, rows 1..17
    else if (tid < 49) eidx = 17*18 + (tid-32);      // row 17, cols 1..16

    float geo = 0.0f, var = 0.0f, ab2 = 0.0f;
    float dot4[4] = {0.f,0.f,0.f,0.f};
    float ownss = 0.0f, ess = 0.0f;

    for (int ck = 0; ck < 8; ck++){
        int c0 = ck*16;
        __syncthreads();
        for (int idx = tid; idx < 1296; idx += 256){
            int cell = idx >> 2, q = idx & 3;
            int r = cell / 18, col = cell % 18;
            int gh = bh + r - 1, gw = bw + col - 1;
            float4 v = make_float4(0.f,0.f,0.f,0.f);
            if ((unsigned)gh < HH && (unsigned)gw < WW)
                v = *(const float4*)(f + (size_t)(gh*WW+gw)*CC + c0 + q*4);
            float* sp = s + cell*17 + q*4;
            sp[0]=v.x; sp[1]=v.y; sp[2]=v.z; sp[3]=v.w;
        }
        __syncthreads();

        #pragma unroll
        for (int ch = 0; ch < 16; ch++){
            float v00 = s[(base-19)*17+ch], v01 = s[(base-18)*17+ch], v02 = s[(base-17)*17+ch];
            float v10 = s[(base- 1)*17+ch], v11 = s[(base   )*17+ch], v12 = s[(base+ 1)*17+ch];
            float v20 = s[(base+17)*17+ch], v21 = s[(base+18)*17+ch], v22 = s[(base+19)*17+ch];
            float gx = (v02 - v00) + 2.0f*(v12 - v10) + (v22 - v20);
            float gy = (v20 - v00) + 2.0f*(v21 - v01) + (v22 - v02);
            geo += sqrtf(gx*gx + gy*gy);
            ownss   = fmaf(v11, v11, ownss);
            dot4[0] = fmaf(v11, v12, dot4[0]);   // (0, 1)
            dot4[1] = fmaf(v11, v20, dot4[1]);   // (1,-1)
            dot4[2] = fmaf(v11, v21, dot4[2]);   // (1, 0)
            dot4[3] = fmaf(v11, v22, dot4[3]);   // (1, 1)
            int c = c0 + ch;
            if (c >= 64){
                float xs = v00+v01+v02+v10+v11+v12+v20+v21+v22;
                float x2 = v00*v00+v01*v01+v02*v02+v10*v10+v11*v11+v12*v12+v20*v20+v21*v21+v22*v22;
                float m1 = xs * (1.0f/9.0f);
                var += x2 * (1.0f/9.0f) - m1*m1;
            } else {
                float d = v11 - g_endlf[c];
                ab2 += d*d;
            }
        }
        if (tid < 49){
            const float* eb = s + eidx*17;
            #pragma unroll
            for (int ch=0; ch<16; ch++) ess = fmaf(eb[ch], eb[ch], ess);
        }
    }

    int px = (bh+ty)*WW + (bw+tx);
    g_geo [px] = geo * (1.0f/128.0f);
    g_var [px] = var;
    g_abs2[px] = ab2;

    __syncthreads();
    snorm[base] = ownss;
    if (tid < 49) snorm[eidx] = ess;
    __syncthreads();

    int h = bh + ty, w = bw + tx;
    float invp = 1.0f / fmaxf(sqrtf(ownss), 1e-12f);
    const int nbo[4] = {1, 17, 18, 19};
    const int ddx[4] = {0,1,1,1};
    const int ddy[4] = {1,-1,0,1};
    #pragma unroll
    for (int d=0; d<4; d++){
        int i = 4 + d;
        int nh = h + ddx[d], nw = w + ddy[d];
        if ((unsigned)nh < HH && (unsigned)nw < WW){
            float nn = snorm[base + nbo[d]];
            float val = 1.0f - dot4[d] * invp / fmaxf(sqrtf(nn), 1e-12f);
            int npx = nh*WW + nw;
            g_cost[(size_t)px *8 + i]          = val;
            out   [(size_t)px *10 + 1 + i]     = val;
            g_cost[(size_t)npx*8 + (7-i)]      = val;
            out   [(size_t)npx*10 + 1 + (7-i)] = val;
        } else {
            g_cost[(size_t)px*8 + i]      = BIGF;
            out   [(size_t)px*10 + 1 + i] = BIGF;
        }
    }
    const int udx[4] = {-1,-1,-1, 0};
    const int udy[4] = {-1, 0, 1,-1};
    #pragma unroll
    for (int j=0; j<4; j++){
        int nh = h + udx[j], nw = w + udy[j];
        if (!((unsigned)nh < HH && (unsigned)nw < WW)){
            g_cost[(size_t)px*8 + j]      = BIGF;
            out   [(size_t)px*10 + 1 + j] = BIGF;
        }
    }
}

// ---------------- MLP: f32x2 packed FFMA, 2 px/thread ----------------
__global__ void mlp_k(const float* __restrict__ f, const float* __restrict__ w1,
                      const float* __restrict__ b1, const float* __restrict__ w2,
                      const float* __restrict__ b2){
    __shared__ __align__(16) float sw[CC*32];    // 16 KB
    __shared__ float sf[512*9];
    int tid = threadIdx.x;
    int pxbase = blockIdx.x*512;

    for (int i = tid; i < 1024; i += 256)
        *(float4*)(sw + i*4) = *(const float4*)(w1 + i*4);

    unsigned long long acc0[16], acc1[16];
    #pragma unroll
    for (int j=0;j<16;j++){
        unsigned long long b = pk2(b1[2*j], b1[2*j+1]);
        acc0[j] = b; acc1[j] = b;
    }

    for (int ck = 0; ck < 16; ck++){
        int c0 = ck*8;
        __syncthreads();
        for (int idx = tid; idx < 1024; idx += 256){
            int p = idx >> 1, q = idx & 1;
            float4 v = *(const float4*)(f + (size_t)(pxbase+p)*CC + c0 + q*4);
            float* sp = sf + p*9 + q*4;
            sp[0]=v.x; sp[1]=v.y; sp[2]=v.z; sp[3]=v.w;
        }
        __syncthreads();
        #pragma unroll
        for (int c = 0; c < 8; c++){
            float fa = sf[tid*9 + c];
            float fb = sf[(tid+256)*9 + c];
            unsigned long long fa2 = pk2(fa, fa);
            unsigned long long fb2 = pk2(fb, fb);
            const ulonglong2* wr = (const ulonglong2*)(sw + (c0 + c)*32);
            #pragma unroll
            for (int q = 0; q < 8; q++){
                ulonglong2 wv = wr[q];
                fma2(acc0[2*q  ], fa2, wv.x);
                fma2(acc0[2*q+1], fa2, wv.y);
                fma2(acc1[2*q  ], fb2, wv.x);
                fma2(acc1[2*q+1], fb2, wv.y);
            }
        }
    }
    float z0 = b2[0], z1 = z0;
    #pragma unroll
    for (int j=0;j<16;j++){
        float2 u0 = upk2(acc0[j]);
        float2 u1 = upk2(acc1[j]);
        float wa = w2[2*j], wb = w2[2*j+1];
        z0 = fmaf(fmaxf(u0.x, 0.0f), wa, z0);
        z0 = fmaf(fmaxf(u0.y, 0.0f), wb, z0);
        z1 = fmaf(fmaxf(u1.x, 0.0f), wa, z1);
        z1 = fmaf(fmaxf(u1.y, 0.0f), wb, z1);
    }
    g_omega[pxbase + tid]       = 1.0f / (1.0f + expf(-z0));
    g_omega[pxbase + tid + 256] = 1.0f / (1.0f + expf(-z1));
}

// ---------------- persistent relaxation + fused final pack ---------------------
// 121 blocks, 800 threads, 24x24 tile + 8 halo, 32 phases x 8 fused iterations.
// Phase 0 inits SMEM directly (BIG except start). Phases >0 reload only the
// 1024-cell halo ring; the 24x24 interior is retained in SMEM (== stored dst).
// Tree-min shortens the per-update dependency chain ~64 -> ~20 cycles.
__global__ void __launch_bounds__(800,1) dist_relax_persist(const int* __restrict__ startn,
                                                            const int* __restrict__ endn,
                                                            float* __restrict__ out){
    __shared__ __align__(16) float sd[2][42][44];
    int tid = threadIdx.x;
    int tx = tid % 20, ty = tid / 20;     // region row ty (0..39); cells cols 2tx,2tx+1
    int bh = blockIdx.y*24 - 8, bw = blockIdx.x*24 - 8;
    const unsigned NBLK = 121u;

    // BIG frame (never written by iterations)
    for (int idx = tid; idx < 2*42*44; idx += 800){
        int l = idx / (42*44);
        int rem = idx % (42*44);
        int r = rem / 44, c = rem % 44;
        if (r == 0 || r == 41 || c == 0 || c >= 41)
            sd[l][r][c] = BIGF;
    }

    float cst[2][8];
    #pragma unroll
    for (int b=0;b<2;b++){
        int gh = bh + ty, gw = bw + 2*tx + b;
        if ((unsigned)gh < HH && (unsigned)gw < WW){
            const float4* cp = (const float4*)(g_cost + (size_t)(gh*WW+gw)*8);
            float4 u = __ldg(cp), w = __ldg(cp+1);
            cst[b][0]=u.x; cst[b][1]=u.y; cst[b][2]=u.z; cst[b][3]=u.w;
            cst[b][4]=w.x; cst[b][5]=w.y; cst[b][6]=w.z; cst[b][7]=w.w;
        } else {
            #pragma unroll
            for (int i=0;i<8;i++) cst[b][i] = BIGF;
        }
    }

    // phase 0: init region in SMEM (no global read of dist needed)
    {
        int sh = startn[0], sw_ = startn[1];
        for (int idx = tid; idx < 1600; idx += 800){
            int r = idx / 40, c = idx % 40;
            int gh = bh + r, gw = bw + c;
            sd[0][r+1][c+1] = (gh == sh && gw == sw_) ? 0.0f : BIGF;
        }
    }

    #pragma unroll 1
    for (int p = 0; p < 32; p++){
        float* __restrict__ dst = g_dist[(p+1) & 1];

        if (p > 0){
            const float* __restrict__ src = g_dist[p & 1];
            // reload only the halo ring (1024 cells); interior retained in SMEM
            for (int idx = tid; idx < 1024; idx += 800){
                int r, c;
                if (idx < 320)      { r = idx/40;            c = idx%40; }
                else if (idx < 640) { int t = idx-320; r = 32 + t/40; c = t%40; }
                else if (idx < 832) { int t = idx-640; r = 8 + t/8;   c = t%8; }
                else                { int t = idx-832; r = 8 + t/8;   c = 32 + t%8; }
                int gh = bh + r, gw = bw + c;
                float v = BIGF;
                if ((unsigned)gh < HH && (unsigned)gw < WW)
                    v = __ldcg(src + gh*WW + gw);
                sd[0][r+1][c+1] = v;
            }
        }
        __syncthreads();

        #pragma unroll
        for (int it = 0; it < 8; it++){
            const int cur = it & 1;
            bool act = (ty >= 1+it) && (ty <= 38-it) &&
                       (2*tx+1 >= 1+it) && (2*tx <= 38-it);
            if (act){
                float2 a0 = *(const float2*)&sd[cur][ty  ][2*tx];
                float2 a1 = *(const float2*)&sd[cur][ty  ][2*tx+2];
                float2 b0 = *(const float2*)&sd[cur][ty+1][2*tx];
                float2 b1 = *(const float2*)&sd[cur][ty+1][2*tx+2];
                float2 c0 = *(const float2*)&sd[cur][ty+2][2*tx];
                float2 c1 = *(const float2*)&sd[cur][ty+2][2*tx+2];

                float s0 = a0.x + cst[0][0];
                float s1 = a0.y + cst[0][1];
                float s2 = a1.x + cst[0][2];
                float s3 = b0.x + cst[0][3];
                float s4 = b1.x + cst[0][4];
                float s5 = c0.x + cst[0][5];
                float s6 = c0.y + cst[0][6];
                float s7 = c1.x + cst[0][7];
                float v0 = fminf(b0.y,
                           fminf(fminf(fminf(s0,s1), fminf(s2,s3)),
                                 fminf(fminf(s4,s5), fminf(s6,s7))));

                float t0 = a0.y + cst[1][0];
                float t1 = a1.x + cst[1][1];
                float t2 = a1.y + cst[1][2];
                float t3 = b0.y + cst[1][3];
                float t4 = b1.y + cst[1][4];
                float t5 = c0.y + cst[1][5];
                float t6 = c1.x + cst[1][6];
                float t7 = c1.y + cst[1][7];
                float v1 = fminf(b1.x,
                           fminf(fminf(fminf(t0,t1), fminf(t2,t3)),
                                 fminf(fminf(t4,t5), fminf(t6,t7))));

                sd[cur^1][ty+1][2*tx+1] = v0;
                sd[cur^1][ty+1][2*tx+2] = v1;
            }
            __syncthreads();
        }
        // 8 iterations (even) -> exact interior in sd[0], region rows/cols [8,31]

        if (p < 31){
            if (ty >= 8 && ty < 32 && tx >= 4 && tx < 16){
                int gh = bh + ty, gw = bw + 2*tx;
                if (gh < HH && gw < WW){
                    __stcg(dst + gh*WW + gw,     sd[0][ty+1][2*tx+1]);
                    __stcg(dst + gh*WW + gw + 1, sd[0][ty+1][2*tx+2]);
                }
            }
            __threadfence();
            __syncthreads();
            if (tid == 0){
                atomicAdd(&g_arrive, 1u);
                unsigned target = NBLK * (unsigned)(p + 1);
                while (*((volatile unsigned*)&g_arrive) < target) __nanosleep(64);
            }
            __syncthreads();
        } else {
            // final phase: write output directly (heuristic + dist)
            if (ty >= 8 && ty < 32 && tx >= 4 && tx < 16){
                int gh = bh + ty, gw = bw + 2*tx;
                if (gh < HH && gw < WW){
                    int e = endn[0]*WW + endn[1];
                    float varEnd = g_var[e];
                    float s0 = g_scal[0], s1 = g_scal[1], s2 = g_scal[2];
                    #pragma unroll
                    for (int b=0; b<2; b++){
                        int px = gh*WW + gw + b;
                        float om = g_omega[px];
                        float hv = s0*g_geo[px]
                                 + om*s1*(varEnd - g_var[px])
                                 + (1.0f - om)*s2*sqrtf(g_abs2[px]);
                        out[(size_t)px*10 + 0] = fmaxf(hv, 0.0f);
                        out[(size_t)px*10 + 9] = fminf(sd[0][ty+1][2*tx+1+b], BIGF);
                    }
                }
            }
        }
    }
}

// ---------------- launch ----------------
extern "C" void kernel_launch(void* const* d_in, const int* in_sizes, int n_in,
                              void* d_out, int out_size){
    const float* f = (const float*)d_in[0];
    float* out = (float*)d_out;

    k0<<<1,64>>>(f, (const float*)d_in[1], (const float*)d_in[2],
                 (const float*)d_in[3], (const int*)d_in[9]);
    hc_k<<<dim3(16,16), 256>>>(f, out);
    mlp_k<<<128, 256>>>(f, (const float*)d_in[4], (const float*)d_in[5],
                        (const float*)d_in[6], (const float*)d_in[7]);
    dist_relax_persist<<<dim3(11,11), 800>>>((const int*)d_in[8],
                                             (const int*)d_in[9], out);
}

// round 7
// speedup vs baseline: 1.5837x; 1.0692x over previous
#include <cuda_runtime.h>
#include <math.h>

#define HH 256
#define WW 256
#define CC 128
#define BIGF 1000000000.0f

// ---------------- device scratch ----------------
__device__ float g_cost[HH*WW*8];
__device__ float g_dist[2][HH*WW];
__device__ float g_geo [HH*WW];
__device__ float g_var [HH*WW];
__device__ float g_abs2[HH*WW];
__device__ float g_omega[HH*WW];
__device__ float g_endlf[64];
__device__ float g_scal[3];
__device__ unsigned g_arrive;

__device__ __forceinline__ float softplusf(float x){
    return x > 30.0f ? x : log1pf(expf(x));
}

// packed f32x2 helpers (Blackwell)
__device__ __forceinline__ unsigned long long pk2(float x, float y){
    unsigned long long r;
    asm("mov.b64 %0, {%1, %2};" : "=l"(r) : "f"(x), "f"(y));
    return r;
}
__device__ __forceinline__ void fma2(unsigned long long &d, unsigned long long a,
                                     unsigned long long b){
    asm("fma.rn.f32x2 %0, %1, %2, %0;" : "+l"(d) : "l"(a), "l"(b));
}
__device__ __forceinline__ float2 upk2(unsigned long long v){
    float2 r;
    asm("mov.b64 {%0, %1}, %2;" : "=f"(r.x), "=f"(r.y) : "l"(v));
    return r;
}

// ---------------- kernel 0 ----------------
__global__ void k0(const float* __restrict__ f, const float* dl, const float* gm,
                   const float* bt, const int* __restrict__ endn){
    int t = threadIdx.x;
    if (t == 0){
        g_scal[0] = softplusf(*dl);
        g_scal[1] = softplusf(*gm);
        g_scal[2] = softplusf(*bt);
        g_arrive  = 0u;
    }
    int e = endn[0]*WW + endn[1];
    if (t < 64) g_endlf[t] = f[(size_t)e*CC + t];
}

// ---------------- fused heuristic + cost ----------------
// DIRS: 0:(-1,-1) 1:(-1,0) 2:(-1,1) 3:(0,-1) 4:(0,1) 5:(1,-1) 6:(1,0) 7:(1,1)
// cost[p][i] == cost[p+d_i][7-i]; compute i=4..7, mirror-write.
__global__ void hc_k(const float* __restrict__ f, float* __restrict__ out){
    __shared__ float s[324*17];          // 18x18 cells x 16 ch, pad 17
    __shared__ float snorm[324];
    int tid = threadIdx.x;
    int tx = tid & 15, ty = tid >> 4;
    int bh = blockIdx.y*16, bw = blockIdx.x*16;
    int base = (ty+1)*18 + (tx+1);

    int eidx = -1;
    if (tid < 16)      eidx = (tid+2)*18;            // col 0, rows 2..17
    else if (tid < 33) eidx = (tid-15)*18 + 17;      // col 17, rows 1..17
    else if (tid < 49) eidx = 17*18 + (tid-32);      // row 17, cols 1..16

    float geo = 0.0f, var = 0.0f, ab2 = 0.0f;
    float dot4[4] = {0.f,0.f,0.f,0.f};
    float ownss = 0.0f, ess = 0.0f;

    for (int ck = 0; ck < 8; ck++){
        int c0 = ck*16;
        __syncthreads();
        for (int idx = tid; idx < 1296; idx += 256){
            int cell = idx >> 2, q = idx & 3;
            int r = cell / 18, col = cell % 18;
            int gh = bh + r - 1, gw = bw + col - 1;
            float4 v = make_float4(0.f,0.f,0.f,0.f);
            if ((unsigned)gh < HH && (unsigned)gw < WW)
                v = *(const float4*)(f + (size_t)(gh*WW+gw)*CC + c0 + q*4);
            float* sp = s + cell*17 + q*4;
            sp[0]=v.x; sp[1]=v.y; sp[2]=v.z; sp[3]=v.w;
        }
        __syncthreads();

        #pragma unroll
        for (int ch = 0; ch < 16; ch++){
            float v00 = s[(base-19)*17+ch], v01 = s[(base-18)*17+ch], v02 = s[(base-17)*17+ch];
            float v10 = s[(base- 1)*17+ch], v11 = s[(base   )*17+ch], v12 = s[(base+ 1)*17+ch];
            float v20 = s[(base+17)*17+ch], v21 = s[(base+18)*17+ch], v22 = s[(base+19)*17+ch];
            float gx = (v02 - v00) + 2.0f*(v12 - v10) + (v22 - v20);
            float gy = (v20 - v00) + 2.0f*(v21 - v01) + (v22 - v02);
            geo += sqrtf(gx*gx + gy*gy);
            ownss   = fmaf(v11, v11, ownss);
            dot4[0] = fmaf(v11, v12, dot4[0]);   // (0, 1)
            dot4[1] = fmaf(v11, v20, dot4[1]);   // (1,-1)
            dot4[2] = fmaf(v11, v21, dot4[2]);   // (1, 0)
            dot4[3] = fmaf(v11, v22, dot4[3]);   // (1, 1)
            int c = c0 + ch;
            if (c >= 64){
                float xs = v00+v01+v02+v10+v11+v12+v20+v21+v22;
                float x2 = v00*v00+v01*v01+v02*v02+v10*v10+v11*v11+v12*v12+v20*v20+v21*v21+v22*v22;
                float m1 = xs * (1.0f/9.0f);
                var += x2 * (1.0f/9.0f) - m1*m1;
            } else {
                float d = v11 - g_endlf[c];
                ab2 += d*d;
            }
        }
        if (tid < 49){
            const float* eb = s + eidx*17;
            #pragma unroll
            for (int ch=0; ch<16; ch++) ess = fmaf(eb[ch], eb[ch], ess);
        }
    }

    int px = (bh+ty)*WW + (bw+tx);
    g_geo [px] = geo * (1.0f/128.0f);
    g_var [px] = var;
    g_abs2[px] = ab2;

    __syncthreads();
    snorm[base] = ownss;
    if (tid < 49) snorm[eidx] = ess;
    __syncthreads();

    int h = bh + ty, w = bw + tx;
    float invp = 1.0f / fmaxf(sqrtf(ownss), 1e-12f);
    const int nbo[4] = {1, 17, 18, 19};
    const int ddx[4] = {0,1,1,1};
    const int ddy[4] = {1,-1,0,1};
    #pragma unroll
    for (int d=0; d<4; d++){
        int i = 4 + d;
        int nh = h + ddx[d], nw = w + ddy[d];
        if ((unsigned)nh < HH && (unsigned)nw < WW){
            float nn = snorm[base + nbo[d]];
            float val = 1.0f - dot4[d] * invp / fmaxf(sqrtf(nn), 1e-12f);
            int npx = nh*WW + nw;
            g_cost[(size_t)px *8 + i]          = val;
            out   [(size_t)px *10 + 1 + i]     = val;
            g_cost[(size_t)npx*8 + (7-i)]      = val;
            out   [(size_t)npx*10 + 1 + (7-i)] = val;
        } else {
            g_cost[(size_t)px*8 + i]      = BIGF;
            out   [(size_t)px*10 + 1 + i] = BIGF;
        }
    }
    const int udx[4] = {-1,-1,-1, 0};
    const int udy[4] = {-1, 0, 1,-1};
    #pragma unroll
    for (int j=0; j<4; j++){
        int nh = h + udx[j], nw = w + udy[j];
        if (!((unsigned)nh < HH && (unsigned)nw < WW)){
            g_cost[(size_t)px*8 + j]      = BIGF;
            out   [(size_t)px*10 + 1 + j] = BIGF;
        }
    }
}

// ---------------- MLP: f32x2 packed FFMA, 2 px/thread ----------------
__global__ void mlp_k(const float* __restrict__ f, const float* __restrict__ w1,
                      const float* __restrict__ b1, const float* __restrict__ w2,
                      const float* __restrict__ b2){
    __shared__ __align__(16) float sw[CC*32];    // 16 KB
    __shared__ float sf[512*9];
    int tid = threadIdx.x;
    int pxbase = blockIdx.x*512;

    for (int i = tid; i < 1024; i += 256)
        *(float4*)(sw + i*4) = *(const float4*)(w1 + i*4);

    unsigned long long acc0[16], acc1[16];
    #pragma unroll
    for (int j=0;j<16;j++){
        unsigned long long b = pk2(b1[2*j], b1[2*j+1]);
        acc0[j] = b; acc1[j] = b;
    }

    for (int ck = 0; ck < 16; ck++){
        int c0 = ck*8;
        __syncthreads();
        for (int idx = tid; idx < 1024; idx += 256){
            int p = idx >> 1, q = idx & 1;
            float4 v = *(const float4*)(f + (size_t)(pxbase+p)*CC + c0 + q*4);
            float* sp = sf + p*9 + q*4;
            sp[0]=v.x; sp[1]=v.y; sp[2]=v.z; sp[3]=v.w;
        }
        __syncthreads();
        #pragma unroll
        for (int c = 0; c < 8; c++){
            float fa = sf[tid*9 + c];
            float fb = sf[(tid+256)*9 + c];
            unsigned long long fa2 = pk2(fa, fa);
            unsigned long long fb2 = pk2(fb, fb);
            const ulonglong2* wr = (const ulonglong2*)(sw + (c0 + c)*32);
            #pragma unroll
            for (int q = 0; q < 8; q++){
                ulonglong2 wv = wr[q];
                fma2(acc0[2*q  ], fa2, wv.x);
                fma2(acc0[2*q+1], fa2, wv.y);
                fma2(acc1[2*q  ], fb2, wv.x);
                fma2(acc1[2*q+1], fb2, wv.y);
            }
        }
    }
    float z0 = b2[0], z1 = z0;
    #pragma unroll
    for (int j=0;j<16;j++){
        float2 u0 = upk2(acc0[j]);
        float2 u1 = upk2(acc1[j]);
        float wa = w2[2*j], wb = w2[2*j+1];
        z0 = fmaf(fmaxf(u0.x, 0.0f), wa, z0);
        z0 = fmaf(fmaxf(u0.y, 0.0f), wb, z0);
        z1 = fmaf(fmaxf(u1.x, 0.0f), wa, z1);
        z1 = fmaf(fmaxf(u1.y, 0.0f), wb, z1);
    }
    g_omega[pxbase + tid]       = 1.0f / (1.0f + expf(-z0));
    g_omega[pxbase + tid + 256] = 1.0f / (1.0f + expf(-z1));
}

// ---------------- persistent relaxation + fused final pack ---------------------
// 256 blocks x 512 threads, 2 blocks/SM (barrier overlap). Tile 16x16, halo 8
// -> region 32x32, 2 cells/thread. 32 phases x 8 fused iterations; halo-ring
// reload between phases; interior retained in SMEM. Tree-min update.
__global__ void __launch_bounds__(512,2) dist_relax_persist(const int* __restrict__ startn,
                                                            const int* __restrict__ endn,
                                                            float* __restrict__ out){
    __shared__ __align__(16) float sd[2][34][36];
    int tid = threadIdx.x;
    int tx = tid & 15, ty = tid >> 4;     // region row ty (0..31); cells cols 2tx,2tx+1
    int bh = blockIdx.y*16 - 8, bw = blockIdx.x*16 - 8;
    const unsigned NBLK = 256u;

    // BIG frame (never written by iterations)
    for (int idx = tid; idx < 2*34*36; idx += 512){
        int l = idx / (34*36);
        int rem = idx % (34*36);
        int r = rem / 36, c = rem % 36;
        if (r == 0 || r == 33 || c == 0 || c >= 33)
            sd[l][r][c] = BIGF;
    }

    float cst[2][8];
    #pragma unroll
    for (int b=0;b<2;b++){
        int gh = bh + ty, gw = bw + 2*tx + b;
        if ((unsigned)gh < HH && (unsigned)gw < WW){
            const float4* cp = (const float4*)(g_cost + (size_t)(gh*WW+gw)*8);
            float4 u = __ldg(cp), w = __ldg(cp+1);
            cst[b][0]=u.x; cst[b][1]=u.y; cst[b][2]=u.z; cst[b][3]=u.w;
            cst[b][4]=w.x; cst[b][5]=w.y; cst[b][6]=w.z; cst[b][7]=w.w;
        } else {
            #pragma unroll
            for (int i=0;i<8;i++) cst[b][i] = BIGF;
        }
    }

    // phase 0: init region in SMEM directly
    {
        int sh = startn[0], sw_ = startn[1];
        for (int idx = tid; idx < 1024; idx += 512){
            int r = idx >> 5, c = idx & 31;
            int gh = bh + r, gw = bw + c;
            sd[0][r+1][c+1] = (gh == sh && gw == sw_) ? 0.0f : BIGF;
        }
    }

    #pragma unroll 1
    for (int p = 0; p < 32; p++){
        float* __restrict__ dst = g_dist[(p+1) & 1];

        if (p > 0){
            const float* __restrict__ src = g_dist[p & 1];
            // reload only the halo ring (768 cells); interior [8..23]^2 retained
            for (int idx = tid; idx < 768; idx += 512){
                int r, c;
                if (idx < 256)      { r = idx >> 5;              c = idx & 31; }
                else if (idx < 512) { r = 24 + ((idx-256) >> 5); c = idx & 31; }
                else { int t = idx-512; r = 8 + (t >> 4); int cc = t & 15;
                       c = (cc < 8) ? cc : 16 + cc; }
                int gh = bh + r, gw = bw + c;
                float v = BIGF;
                if ((unsigned)gh < HH && (unsigned)gw < WW)
                    v = __ldcg(src + gh*WW + gw);
                sd[0][r+1][c+1] = v;
            }
        }
        __syncthreads();

        #pragma unroll
        for (int it = 0; it < 8; it++){
            const int cur = it & 1;
            bool act = (ty >= 1+it) && (ty <= 30-it) &&
                       (2*tx+1 >= 1+it) && (2*tx <= 30-it);
            if (act){
                float2 a0 = *(const float2*)&sd[cur][ty  ][2*tx];
                float2 a1 = *(const float2*)&sd[cur][ty  ][2*tx+2];
                float2 b0 = *(const float2*)&sd[cur][ty+1][2*tx];
                float2 b1 = *(const float2*)&sd[cur][ty+1][2*tx+2];
                float2 c0 = *(const float2*)&sd[cur][ty+2][2*tx];
                float2 c1 = *(const float2*)&sd[cur][ty+2][2*tx+2];

                float s0 = a0.x + cst[0][0];
                float s1 = a0.y + cst[0][1];
                float s2 = a1.x + cst[0][2];
                float s3 = b0.x + cst[0][3];
                float s4 = b1.x + cst[0][4];
                float s5 = c0.x + cst[0][5];
                float s6 = c0.y + cst[0][6];
                float s7 = c1.x + cst[0][7];
                float v0 = fminf(b0.y,
                           fminf(fminf(fminf(s0,s1), fminf(s2,s3)),
                                 fminf(fminf(s4,s5), fminf(s6,s7))));

                float t0 = a0.y + cst[1][0];
                float t1 = a1.x + cst[1][1];
                float t2 = a1.y + cst[1][2];
                float t3 = b0.y + cst[1][3];
                float t4 = b1.y + cst[1][4];
                float t5 = c0.y + cst[1][5];
                float t6 = c1.x + cst[1][6];
                float t7 = c1.y + cst[1][7];
                float v1 = fminf(b1.x,
                           fminf(fminf(fminf(t0,t1), fminf(t2,t3)),
                                 fminf(fminf(t4,t5), fminf(t6,t7))));

                sd[cur^1][ty+1][2*tx+1] = v0;
                sd[cur^1][ty+1][2*tx+2] = v1;
            }
            __syncthreads();
        }
        // 8 iterations (even) -> exact interior in sd[0], region rows/cols [8,23]

        if (p < 31){
            if (ty >= 8 && ty < 24 && tx >= 4 && tx < 12){
                int gh = bh + ty, gw = bw + 2*tx;
                __stcg(dst + gh*WW + gw,     sd[0][ty+1][2*tx+1]);
                __stcg(dst + gh*WW + gw + 1, sd[0][ty+1][2*tx+2]);
            }
            __threadfence();
            __syncthreads();
            if (tid == 0){
                atomicAdd(&g_arrive, 1u);
                unsigned target = NBLK * (unsigned)(p + 1);
                while (*((volatile unsigned*)&g_arrive) < target) __nanosleep(64);
            }
            __syncthreads();
        } else {
            // final phase: write output directly (heuristic + dist)
            if (ty >= 8 && ty < 24 && tx >= 4 && tx < 12){
                int gh = bh + ty, gw = bw + 2*tx;
                int e = endn[0]*WW + endn[1];
                float varEnd = g_var[e];
                float s0 = g_scal[0], s1 = g_scal[1], s2 = g_scal[2];
                #pragma unroll
                for (int b=0; b<2; b++){
                    int px = gh*WW + gw + b;
                    float om = g_omega[px];
                    float hv = s0*g_geo[px]
                             + om*s1*(varEnd - g_var[px])
                             + (1.0f - om)*s2*sqrtf(g_abs2[px]);
                    out[(size_t)px*10 + 0] = fmaxf(hv, 0.0f);
                    out[(size_t)px*10 + 9] = fminf(sd[0][ty+1][2*tx+1+b], BIGF);
                }
            }
        }
    }
}

// ---------------- launch ----------------
extern "C" void kernel_launch(void* const* d_in, const int* in_sizes, int n_in,
                              void* d_out, int out_size){
    const float* f = (const float*)d_in[0];
    float* out = (float*)d_out;

    k0<<<1,64>>>(f, (const float*)d_in[1], (const float*)d_in[2],
                 (const float*)d_in[3], (const int*)d_in[9]);
    hc_k<<<dim3(16,16), 256>>>(f, out);
    mlp_k<<<128, 256>>>(f, (const float*)d_in[4], (const float*)d_in[5],
                        (const float*)d_in[6], (const float*)d_in[7]);
    dist_relax_persist<<<dim3(16,16), 512>>>((const int*)d_in[8],
                                             (const int*)d_in[9], out);
}

// round 8
// speedup vs baseline: 1.7665x; 1.1154x over previous
#include <cuda_runtime.h>
#include <math.h>

#define HH 256
#define WW 256
#define CC 128
#define BIGF 1000000000.0f

// ---------------- device scratch ----------------
__device__ float g_cost[HH*WW*8];
__device__ float g_dist[2][HH*WW];
__device__ float g_geo [HH*WW];
__device__ float g_var [HH*WW];
__device__ float g_abs2[HH*WW];
__device__ float g_omega[HH*WW];
__device__ float g_endlf[64];
__device__ float g_scal[3];
__device__ unsigned g_arrive;

__device__ __forceinline__ float softplusf(float x){
    return x > 30.0f ? x : log1pf(expf(x));
}

// packed f32x2 helpers (Blackwell)
__device__ __forceinline__ unsigned long long pk2(float x, float y){
    unsigned long long r;
    asm("mov.b64 %0, {%1, %2};" : "=l"(r) : "f"(x), "f"(y));
    return r;
}
__device__ __forceinline__ void fma2(unsigned long long &d, unsigned long long a,
                                     unsigned long long b){
    asm("fma.rn.f32x2 %0, %1, %2, %0;" : "+l"(d) : "l"(a), "l"(b));
}
__device__ __forceinline__ float2 upk2(unsigned long long v){
    float2 r;
    asm("mov.b64 {%0, %1}, %2;" : "=f"(r.x), "=f"(r.y) : "l"(v));
    return r;
}

// ---------------- kernel 0 ----------------
__global__ void k0(const float* __restrict__ f, const float* dl, const float* gm,
                   const float* bt, const int* __restrict__ endn){
    int t = threadIdx.x;
    if (t == 0){
        g_scal[0] = softplusf(*dl);
        g_scal[1] = softplusf(*gm);
        g_scal[2] = softplusf(*bt);
        g_arrive  = 0u;
    }
    int e = endn[0]*WW + endn[1];
    if (t < 64) g_endlf[t] = f[(size_t)e*CC + t];
}

// ---------------- fused heuristic + cost + MLP + dist BIG-init ----------------
// DIRS: 0:(-1,-1) 1:(-1,0) 2:(-1,1) 3:(0,-1) 4:(0,1) 5:(1,-1) 6:(1,0) 7:(1,1)
// cost[p][i] == cost[p+d_i][7-i]; compute i=4..7, mirror-write.
__global__ void hc_k(const float* __restrict__ f, float* __restrict__ out,
                     const float* __restrict__ w1, const float* __restrict__ b1,
                     const float* __restrict__ w2, const float* __restrict__ b2){
    __shared__ float s[324*17];              // 18x18 cells x 16 ch, pad 17
    __shared__ float snorm[324];
    __shared__ __align__(16) float sw[CC*32];// W1, 16 KB
    int tid = threadIdx.x;
    int tx = tid & 15, ty = tid >> 4;
    int bh = blockIdx.y*16, bw = blockIdx.x*16;
    int base = (ty+1)*18 + (tx+1);

    for (int i = tid; i < 1024; i += 256)
        *(float4*)(sw + i*4) = *(const float4*)(w1 + i*4);

    int eidx = -1;
    if (tid < 16)      eidx = (tid+2)*18;            // col 0, rows 2..17
    else if (tid < 33) eidx = (tid-15)*18 + 17;      // col 17, rows 1..17
    else if (tid < 49) eidx = 17*18 + (tid-32);      // row 17, cols 1..16

    float geo = 0.0f, var = 0.0f, ab2 = 0.0f;
    float dot4[4] = {0.f,0.f,0.f,0.f};
    float ownss = 0.0f, ess = 0.0f;

    unsigned long long macc[16];
    #pragma unroll
    for (int j=0;j<16;j++) macc[j] = pk2(b1[2*j], b1[2*j+1]);

    for (int ck = 0; ck < 8; ck++){
        int c0 = ck*16;
        __syncthreads();
        for (int idx = tid; idx < 1296; idx += 256){
            int cell = idx >> 2, q = idx & 3;
            int r = cell / 18, col = cell % 18;
            int gh = bh + r - 1, gw = bw + col - 1;
            float4 v = make_float4(0.f,0.f,0.f,0.f);
            if ((unsigned)gh < HH && (unsigned)gw < WW)
                v = *(const float4*)(f + (size_t)(gh*WW+gw)*CC + c0 + q*4);
            float* sp = s + cell*17 + q*4;
            sp[0]=v.x; sp[1]=v.y; sp[2]=v.z; sp[3]=v.w;
        }
        __syncthreads();

        #pragma unroll
        for (int ch = 0; ch < 16; ch++){
            float v00 = s[(base-19)*17+ch], v01 = s[(base-18)*17+ch], v02 = s[(base-17)*17+ch];
            float v10 = s[(base- 1)*17+ch], v11 = s[(base   )*17+ch], v12 = s[(base+ 1)*17+ch];
            float v20 = s[(base+17)*17+ch], v21 = s[(base+18)*17+ch], v22 = s[(base+19)*17+ch];
            float gx = (v02 - v00) + 2.0f*(v12 - v10) + (v22 - v20);
            float gy = (v20 - v00) + 2.0f*(v21 - v01) + (v22 - v02);
            geo += sqrtf(gx*gx + gy*gy);
            ownss   = fmaf(v11, v11, ownss);
            dot4[0] = fmaf(v11, v12, dot4[0]);   // (0, 1)
            dot4[1] = fmaf(v11, v20, dot4[1]);   // (1,-1)
            dot4[2] = fmaf(v11, v21, dot4[2]);   // (1, 0)
            dot4[3] = fmaf(v11, v22, dot4[3]);   // (1, 1)
            // MLP layer-1 rides the same register (v11 = own-pixel channel value)
            {
                unsigned long long f2 = pk2(v11, v11);
                const ulonglong2* wr = (const ulonglong2*)(sw + (c0 + ch)*32);
                #pragma unroll
                for (int q = 0; q < 8; q++){
                    ulonglong2 wv = wr[q];
                    fma2(macc[2*q  ], f2, wv.x);
                    fma2(macc[2*q+1], f2, wv.y);
                }
            }
            int c = c0 + ch;
            if (c >= 64){
                float xs = v00+v01+v02+v10+v11+v12+v20+v21+v22;
                float x2 = v00*v00+v01*v01+v02*v02+v10*v10+v11*v11+v12*v12+v20*v20+v21*v21+v22*v22;
                float m1 = xs * (1.0f/9.0f);
                var += x2 * (1.0f/9.0f) - m1*m1;
            } else {
                float d = v11 - g_endlf[c];
                ab2 += d*d;
            }
        }
        if (tid < 49){
            const float* eb = s + eidx*17;
            #pragma unroll
            for (int ch=0; ch<16; ch++) ess = fmaf(eb[ch], eb[ch], ess);
        }
    }

    int px = (bh+ty)*WW + (bw+tx);
    g_geo [px] = geo * (1.0f/128.0f);
    g_var [px] = var;
    g_abs2[px] = ab2;
    g_dist[0][px] = BIGF;                 // BIG-init both dist buffers
    g_dist[1][px] = BIGF;

    // MLP layer 2 + sigmoid
    {
        float z = b2[0];
        #pragma unroll
        for (int j=0;j<16;j++){
            float2 u = upk2(macc[j]);
            z = fmaf(fmaxf(u.x, 0.0f), w2[2*j],   z);
            z = fmaf(fmaxf(u.y, 0.0f), w2[2*j+1], z);
        }
        g_omega[px] = 1.0f / (1.0f + expf(-z));
    }

    __syncthreads();
    snorm[base] = ownss;
    if (tid < 49) snorm[eidx] = ess;
    __syncthreads();

    int h = bh + ty, w = bw + tx;
    float invp = 1.0f / fmaxf(sqrtf(ownss), 1e-12f);
    const int nbo[4] = {1, 17, 18, 19};
    const int ddx[4] = {0,1,1,1};
    const int ddy[4] = {1,-1,0,1};
    #pragma unroll
    for (int d=0; d<4; d++){
        int i = 4 + d;
        int nh = h + ddx[d], nw = w + ddy[d];
        if ((unsigned)nh < HH && (unsigned)nw < WW){
            float nn = snorm[base + nbo[d]];
            float val = 1.0f - dot4[d] * invp / fmaxf(sqrtf(nn), 1e-12f);
            int npx = nh*WW + nw;
            g_cost[(size_t)px *8 + i]          = val;
            out   [(size_t)px *10 + 1 + i]     = val;
            g_cost[(size_t)npx*8 + (7-i)]      = val;
            out   [(size_t)npx*10 + 1 + (7-i)] = val;
        } else {
            g_cost[(size_t)px*8 + i]      = BIGF;
            out   [(size_t)px*10 + 1 + i] = BIGF;
        }
    }
    const int udx[4] = {-1,-1,-1, 0};
    const int udy[4] = {-1, 0, 1,-1};
    #pragma unroll
    for (int j=0; j<4; j++){
        int nh = h + udx[j], nw = w + udy[j];
        if (!((unsigned)nh < HH && (unsigned)nw < WW)){
            g_cost[(size_t)px*8 + j]      = BIGF;
            out   [(size_t)px*10 + 1 + j] = BIGF;
        }
    }
}

// ---------------- persistent relaxation + fused final pack ---------------------
// 256 blocks x 512 threads, 2/SM. Tile 16x16, halo 8 -> region 32x32.
// Chebyshev-sparsity skip: after phase p only cells with cheb(start) <= 8(p+1)
// are finite; a block whose whole region is farther skips the phase entirely
// (both dist buffers pre-initialized to BIG, so stale values are exact).
__global__ void __launch_bounds__(512,2) dist_relax_persist(const int* __restrict__ startn,
                                                            const int* __restrict__ endn,
                                                            float* __restrict__ out){
    __shared__ __align__(16) float sd[2][34][36];
    int tid = threadIdx.x;
    int tx = tid & 15, ty = tid >> 4;     // region row ty (0..31); cells cols 2tx,2tx+1
    int bh = blockIdx.y*16 - 8, bw = blockIdx.x*16 - 8;
    const unsigned NBLK = 256u;

    int sh = startn[0], sw_ = startn[1];
    // closed-form Chebyshev distance from start to this block's (clipped) region
    int d0;
    {
        int rlo = max(bh, 0),  rhi = min(bh+31, HH-1);
        int clo = max(bw, 0),  chi = min(bw+31, WW-1);
        int dr = max(max(rlo - sh, sh - rhi), 0);
        int dc = max(max(clo - sw_, sw_ - chi), 0);
        d0 = max(dr, dc);
    }

    // BIG frame (never written by iterations)
    for (int idx = tid; idx < 2*34*36; idx += 512){
        int l = idx / (34*36);
        int rem = idx % (34*36);
        int r = rem / 36, c = rem % 36;
        if (r == 0 || r == 33 || c == 0 || c >= 33)
            sd[l][r][c] = BIGF;
    }

    float cst[2][8];
    #pragma unroll
    for (int b=0;b<2;b++){
        int gh = bh + ty, gw = bw + 2*tx + b;
        if ((unsigned)gh < HH && (unsigned)gw < WW){
            const float4* cp = (const float4*)(g_cost + (size_t)(gh*WW+gw)*8);
            float4 u = __ldg(cp), w = __ldg(cp+1);
            cst[b][0]=u.x; cst[b][1]=u.y; cst[b][2]=u.z; cst[b][3]=u.w;
            cst[b][4]=w.x; cst[b][5]=w.y; cst[b][6]=w.z; cst[b][7]=w.w;
        } else {
            #pragma unroll
            for (int i=0;i<8;i++) cst[b][i] = BIGF;
        }
    }

    // phase 0 base state in SMEM (BIG except start)
    for (int idx = tid; idx < 1024; idx += 512){
        int r = idx >> 5, c = idx & 31;
        int gh = bh + r, gw = bw + c;
        sd[0][r+1][c+1] = (gh == sh && gw == sw_) ? 0.0f : BIGF;
    }

    #pragma unroll 1
    for (int p = 0; p < 32; p++){
        float* __restrict__ dst = g_dist[(p+1) & 1];
        bool skip = (d0 > 8*(p+1));       // whole region provably still BIG

        if (!skip){
            if (p > 0){
                const float* __restrict__ src = g_dist[p & 1];
                // reload only the halo ring (768 cells); interior retained
                for (int idx = tid; idx < 768; idx += 512){
                    int r, c;
                    if (idx < 256)      { r = idx >> 5;              c = idx & 31; }
                    else if (idx < 512) { r = 24 + ((idx-256) >> 5); c = idx & 31; }
                    else { int t = idx-512; r = 8 + (t >> 4); int cc = t & 15;
                           c = (cc < 8) ? cc : 16 + cc; }
                    int gh = bh + r, gw = bw + c;
                    float v = BIGF;
                    if ((unsigned)gh < HH && (unsigned)gw < WW)
                        v = __ldcg(src + gh*WW + gw);
                    sd[0][r+1][c+1] = v;
                }
            }
            __syncthreads();

            #pragma unroll
            for (int it = 0; it < 8; it++){
                const int cur = it & 1;
                bool act = (ty >= 1+it) && (ty <= 30-it) &&
                           (2*tx+1 >= 1+it) && (2*tx <= 30-it);
                if (act){
                    float2 a0 = *(const float2*)&sd[cur][ty  ][2*tx];
                    float2 a1 = *(const float2*)&sd[cur][ty  ][2*tx+2];
                    float2 b0 = *(const float2*)&sd[cur][ty+1][2*tx];
                    float2 b1 = *(const float2*)&sd[cur][ty+1][2*tx+2];
                    float2 c0 = *(const float2*)&sd[cur][ty+2][2*tx];
                    float2 c1 = *(const float2*)&sd[cur][ty+2][2*tx+2];

                    float s0 = a0.x + cst[0][0];
                    float s1 = a0.y + cst[0][1];
                    float s2 = a1.x + cst[0][2];
                    float s3 = b0.x + cst[0][3];
                    float s4 = b1.x + cst[0][4];
                    float s5 = c0.x + cst[0][5];
                    float s6 = c0.y + cst[0][6];
                    float s7 = c1.x + cst[0][7];
                    float v0 = fminf(b0.y,
                               fminf(fminf(fminf(s0,s1), fminf(s2,s3)),
                                     fminf(fminf(s4,s5), fminf(s6,s7))));

                    float t0 = a0.y + cst[1][0];
                    float t1 = a1.x + cst[1][1];
                    float t2 = a1.y + cst[1][2];
                    float t3 = b0.y + cst[1][3];
                    float t4 = b1.y + cst[1][4];
                    float t5 = c0.y + cst[1][5];
                    float t6 = c1.x + cst[1][6];
                    float t7 = c1.y + cst[1][7];
                    float v1 = fminf(b1.x,
                               fminf(fminf(fminf(t0,t1), fminf(t2,t3)),
                                     fminf(fminf(t4,t5), fminf(t6,t7))));

                    sd[cur^1][ty+1][2*tx+1] = v0;
                    sd[cur^1][ty+1][2*tx+2] = v1;
                }
                __syncthreads();
            }
            // 8 iterations (even) -> exact interior in sd[0], rows/cols [8,23]

            if (p < 31){
                if (ty >= 8 && ty < 24 && tx >= 4 && tx < 12){
                    int gh = bh + ty, gw = bw + 2*tx;
                    __stcg(dst + gh*WW + gw,     sd[0][ty+1][2*tx+1]);
                    __stcg(dst + gh*WW + gw + 1, sd[0][ty+1][2*tx+2]);
                }
                __threadfence();
            } else {
                // final phase: write output directly (heuristic + dist)
                if (ty >= 8 && ty < 24 && tx >= 4 && tx < 12){
                    int gh = bh + ty, gw = bw + 2*tx;
                    int e = endn[0]*WW + endn[1];
                    float varEnd = g_var[e];
                    float q0 = g_scal[0], q1 = g_scal[1], q2 = g_scal[2];
                    #pragma unroll
                    for (int b=0; b<2; b++){
                        int px = gh*WW + gw + b;
                        float om = g_omega[px];
                        float hv = q0*g_geo[px]
                                 + om*q1*(varEnd - g_var[px])
                                 + (1.0f - om)*q2*sqrtf(g_abs2[px]);
                        out[(size_t)px*10 + 0] = fmaxf(hv, 0.0f);
                        out[(size_t)px*10 + 9] = fminf(sd[0][ty+1][2*tx+1+b], BIGF);
                    }
                }
            }
        }

        if (p < 31){
            __syncthreads();
            if (tid == 0){
                atomicAdd(&g_arrive, 1u);
                unsigned target = NBLK * (unsigned)(p + 1);
                while (*((volatile unsigned*)&g_arrive) < target) __nanosleep(64);
            }
            __syncthreads();
        }
    }
}

// ---------------- launch ----------------
extern "C" void kernel_launch(void* const* d_in, const int* in_sizes, int n_in,
                              void* d_out, int out_size){
    const float* f = (const float*)d_in[0];
    float* out = (float*)d_out;

    k0<<<1,64>>>(f, (const float*)d_in[1], (const float*)d_in[2],
                 (const float*)d_in[3], (const int*)d_in[9]);
    hc_k<<<dim3(16,16), 256>>>(f, out, (const float*)d_in[4], (const float*)d_in[5],
                               (const float*)d_in[6], (const float*)d_in[7]);
    dist_relax_persist<<<dim3(16,16), 512>>>((const int*)d_in[8],
                                             (const int*)d_in[9], out);
}

// round 10
// speedup vs baseline: 1.7896x; 1.0131x over previous
#include <cuda_runtime.h>
#include <math.h>

#define HH 256
#define WW 256
#define CC 128
#define BIGF 1000000000.0f

// ---------------- device scratch ----------------
__device__ float g_cost[HH*WW*8];
__device__ float g_dist[2][HH*WW];
__device__ float g_geo [HH*WW];
__device__ float g_var [HH*WW];
__device__ float g_abs2[HH*WW];
__device__ float g_omega[HH*WW];
__device__ unsigned g_arrive;

__device__ __forceinline__ float softplusf(float x){
    return x > 30.0f ? x : log1pf(expf(x));
}

// packed f32x2 helpers (Blackwell SIMD2 fp32: add/mul/fma only)
__device__ __forceinline__ unsigned long long pk2(float x, float y){
    unsigned long long r;
    asm("mov.b64 %0, {%1, %2};" : "=l"(r) : "f"(x), "f"(y));
    return r;
}
__device__ __forceinline__ void fma2(unsigned long long &d, unsigned long long a,
                                     unsigned long long b){
    asm("fma.rn.f32x2 %0, %1, %2, %0;" : "+l"(d) : "l"(a), "l"(b));
}
__device__ __forceinline__ unsigned long long add2(unsigned long long a,
                                                   unsigned long long b){
    unsigned long long r;
    asm("add.rn.f32x2 %0, %1, %2;" : "=l"(r) : "l"(a), "l"(b));
    return r;
}
__device__ __forceinline__ float2 upk2(unsigned long long v){
    float2 r;
    asm("mov.b64 {%0, %1}, %2;" : "=f"(r.x), "=f"(r.y) : "l"(v));
    return r;
}

// ---------------- fused heuristic + cost + MLP + dist BIG-init ----------------
// DIRS: 0:(-1,-1) 1:(-1,0) 2:(-1,1) 3:(0,-1) 4:(0,1) 5:(1,-1) 6:(1,0) 7:(1,1)
// cost[p][i] == cost[p+d_i][7-i]; compute i=4..7, mirror-write.
__global__ void hc_k(const float* __restrict__ f, float* __restrict__ out,
                     const float* __restrict__ w1, const float* __restrict__ b1,
                     const float* __restrict__ w2, const float* __restrict__ b2,
                     const int* __restrict__ endn){
    __shared__ float s[324*17];              // 18x18 cells x 16 ch, pad 17
    __shared__ float snorm[324];
    __shared__ __align__(16) float sw[CC*32];// W1, 16 KB
    __shared__ __align__(16) float sendlf[64];
    int tid = threadIdx.x;
    int tx = tid & 15, ty = tid >> 4;
    int bh = blockIdx.y*16, bw = blockIdx.x*16;
    int base = (ty+1)*18 + (tx+1);

    if (tid == 0 && blockIdx.x == 0 && blockIdx.y == 0) g_arrive = 0u;

    for (int i = tid; i < 1024; i += 256)
        *(float4*)(sw + i*4) = *(const float4*)(w1 + i*4);
    if (tid < 16){
        int e = endn[0]*WW + endn[1];
        *(float4*)(sendlf + tid*4) = *(const float4*)(f + (size_t)e*CC + tid*4);
    }

    int eidx = -1;
    if (tid < 16)      eidx = (tid+2)*18;            // col 0, rows 2..17
    else if (tid < 33) eidx = (tid-15)*18 + 17;      // col 17, rows 1..17
    else if (tid < 49) eidx = 17*18 + (tid-32);      // row 17, cols 1..16

    float geo = 0.0f, var = 0.0f, ab2 = 0.0f;
    float dot4[4] = {0.f,0.f,0.f,0.f};
    float ownss = 0.0f, ess = 0.0f;

    unsigned long long macc[16];
    #pragma unroll
    for (int j=0;j<16;j++) macc[j] = pk2(b1[2*j], b1[2*j+1]);

    for (int ck = 0; ck < 8; ck++){
        int c0 = ck*16;
        __syncthreads();
        for (int idx = tid; idx < 1296; idx += 256){
            int cell = idx >> 2, q = idx & 3;
            int r = cell / 18, col = cell % 18;
            int gh = bh + r - 1, gw = bw + col - 1;
            float4 v = make_float4(0.f,0.f,0.f,0.f);
            if ((unsigned)gh < HH && (unsigned)gw < WW)
                v = *(const float4*)(f + (size_t)(gh*WW+gw)*CC + c0 + q*4);
            float* sp = s + cell*17 + q*4;
            sp[0]=v.x; sp[1]=v.y; sp[2]=v.z; sp[3]=v.w;
        }
        __syncthreads();

        #pragma unroll
        for (int ch = 0; ch < 16; ch++){
            float v00 = s[(base-19)*17+ch], v01 = s[(base-18)*17+ch], v02 = s[(base-17)*17+ch];
            float v10 = s[(base- 1)*17+ch], v11 = s[(base   )*17+ch], v12 = s[(base+ 1)*17+ch];
            float v20 = s[(base+17)*17+ch], v21 = s[(base+18)*17+ch], v22 = s[(base+19)*17+ch];
            float gx = (v02 - v00) + 2.0f*(v12 - v10) + (v22 - v20);
            float gy = (v20 - v00) + 2.0f*(v21 - v01) + (v22 - v02);
            geo += sqrtf(gx*gx + gy*gy);
            ownss   = fmaf(v11, v11, ownss);
            dot4[0] = fmaf(v11, v12, dot4[0]);   // (0, 1)
            dot4[1] = fmaf(v11, v20, dot4[1]);   // (1,-1)
            dot4[2] = fmaf(v11, v21, dot4[2]);   // (1, 0)
            dot4[3] = fmaf(v11, v22, dot4[3]);   // (1, 1)
            // MLP layer-1 rides the same register (v11 = own-pixel channel value)
            {
                unsigned long long f2 = pk2(v11, v11);
                const ulonglong2* wr = (const ulonglong2*)(sw + (c0 + ch)*32);
                #pragma unroll
                for (int q = 0; q < 8; q++){
                    ulonglong2 wv = wr[q];
                    fma2(macc[2*q  ], f2, wv.x);
                    fma2(macc[2*q+1], f2, wv.y);
                }
            }
            int c = c0 + ch;
            if (c >= 64){
                float xs = v00+v01+v02+v10+v11+v12+v20+v21+v22;
                float x2 = v00*v00+v01*v01+v02*v02+v10*v10+v11*v11+v12*v12+v20*v20+v21*v21+v22*v22;
                float m1 = xs * (1.0f/9.0f);
                var += x2 * (1.0f/9.0f) - m1*m1;
            } else {
                float d = v11 - sendlf[c];
                ab2 += d*d;
            }
        }
        if (tid < 49){
            const float* eb = s + eidx*17;
            #pragma unroll
            for (int ch=0; ch<16; ch++) ess = fmaf(eb[ch], eb[ch], ess);
        }
    }

    int px = (bh+ty)*WW + (bw+tx);
    g_geo [px] = geo * (1.0f/128.0f);
    g_var [px] = var;
    g_abs2[px] = ab2;
    g_dist[0][px] = BIGF;                 // BIG-init both dist buffers
    g_dist[1][px] = BIGF;

    // MLP layer 2 + sigmoid
    {
        float z = b2[0];
        #pragma unroll
        for (int j=0;j<16;j++){
            float2 u = upk2(macc[j]);
            z = fmaf(fmaxf(u.x, 0.0f), w2[2*j],   z);
            z = fmaf(fmaxf(u.y, 0.0f), w2[2*j+1], z);
        }
        g_omega[px] = 1.0f / (1.0f + expf(-z));
    }

    __syncthreads();
    snorm[base] = ownss;
    if (tid < 49) snorm[eidx] = ess;
    __syncthreads();

    int h = bh + ty, w = bw + tx;
    float invp = 1.0f / fmaxf(sqrtf(ownss), 1e-12f);
    const int nbo[4] = {1, 17, 18, 19};
    const int ddx[4] = {0,1,1,1};
    const int ddy[4] = {1,-1,0,1};
    #pragma unroll
    for (int d=0; d<4; d++){
        int i = 4 + d;
        int nh = h + ddx[d], nw = w + ddy[d];
        if ((unsigned)nh < HH && (unsigned)nw < WW){
            float nn = snorm[base + nbo[d]];
            float val = 1.0f - dot4[d] * invp / fmaxf(sqrtf(nn), 1e-12f);
            int npx = nh*WW + nw;
            g_cost[(size_t)px *8 + i]          = val;
            out   [(size_t)px *10 + 1 + i]     = val;
            g_cost[(size_t)npx*8 + (7-i)]      = val;
            out   [(size_t)npx*10 + 1 + (7-i)] = val;
        } else {
            g_cost[(size_t)px*8 + i]      = BIGF;
            out   [(size_t)px*10 + 1 + i] = BIGF;
        }
    }
    const int udx[4] = {-1,-1,-1, 0};
    const int udy[4] = {-1, 0, 1,-1};
    #pragma unroll
    for (int j=0; j<4; j++){
        int nh = h + udx[j], nw = w + udy[j];
        if (!((unsigned)nh < HH && (unsigned)nw < WW)){
            g_cost[(size_t)px*8 + j]      = BIGF;
            out   [(size_t)px*10 + 1 + j] = BIGF;
        }
    }
}

// ---------------- persistent relaxation + fused final pack ---------------------
// 256 blocks x 512 threads, 2/SM. Tile 16x16, halo 8 -> region 32x32.
// Chebyshev skip: after phase p only cells with cheb(start) <= 8(p+1) are finite.
// Packed add.rn.f32x2 for the 8 neighbor sums (fma pipe), scalar FMNMX min tree
// (alu pipe) -> the two pipes dual-issue.
__global__ void __launch_bounds__(512,2) dist_relax_persist(const int* __restrict__ startn,
                                                            const int* __restrict__ endn,
                                                            const float* __restrict__ dl,
                                                            const float* __restrict__ gm,
                                                            const float* __restrict__ bt,
                                                            float* __restrict__ out){
    __shared__ __align__(16) float sd[2][34][36];
    int tid = threadIdx.x;
    int tx = tid & 15, ty = tid >> 4;     // region row ty (0..31); cells cols 2tx,2tx+1
    int bh = blockIdx.y*16 - 8, bw = blockIdx.x*16 - 8;
    const unsigned NBLK = 256u;

    int sh = startn[0], sw_ = startn[1];
    int d0;
    {
        int rlo = max(bh, 0),  rhi = min(bh+31, HH-1);
        int clo = max(bw, 0),  chi = min(bw+31, WW-1);
        int dr = max(max(rlo - sh, sh - rhi), 0);
        int dc = max(max(clo - sw_, sw_ - chi), 0);
        d0 = max(dr, dc);
    }

    // BIG frame (never written by iterations)
    for (int idx = tid; idx < 2*34*36; idx += 512){
        int l = idx / (34*36);
        int rem = idx % (34*36);
        int r = rem / 36, c = rem % 36;
        if (r == 0 || r == 33 || c == 0 || c >= 33)
            sd[l][r][c] = BIGF;
    }

    unsigned long long cst2[8];
    {
        float ca[8], cb[8];
        int gh = bh + ty;
        int gw0 = bw + 2*tx, gw1 = gw0 + 1;
        bool ok0 = (unsigned)gh < HH && (unsigned)gw0 < WW;
        bool ok1 = (unsigned)gh < HH && (unsigned)gw1 < WW;
        #pragma unroll
        for (int i=0;i<8;i++){ ca[i] = BIGF; cb[i] = BIGF; }
        if (ok0){
            const float4* cp = (const float4*)(g_cost + (size_t)(gh*WW+gw0)*8);
            float4 u = __ldg(cp), w = __ldg(cp+1);
            ca[0]=u.x; ca[1]=u.y; ca[2]=u.z; ca[3]=u.w;
            ca[4]=w.x; ca[5]=w.y; ca[6]=w.z; ca[7]=w.w;
        }
        if (ok1){
            const float4* cp = (const float4*)(g_cost + (size_t)(gh*WW+gw1)*8);
            float4 u = __ldg(cp), w = __ldg(cp+1);
            cb[0]=u.x; cb[1]=u.y; cb[2]=u.z; cb[3]=u.w;
            cb[4]=w.x; cb[5]=w.y; cb[6]=w.z; cb[7]=w.w;
        }
        #pragma unroll
        for (int i=0;i<8;i++) cst2[i] = pk2(ca[i], cb[i]);
    }

    // phase 0 base state in SMEM (BIG except start)
    for (int idx = tid; idx < 1024; idx += 512){
        int r = idx >> 5, c = idx & 31;
        int gh = bh + r, gw = bw + c;
        sd[0][r+1][c+1] = (gh == sh && gw == sw_) ? 0.0f : BIGF;
    }

    #pragma unroll 1
    for (int p = 0; p < 32; p++){
        float* __restrict__ dst = g_dist[(p+1) & 1];
        bool skip = (d0 > 8*(p+1));

        if (!skip){
            if (p > 0){
                const float* __restrict__ src = g_dist[p & 1];
                for (int idx = tid; idx < 768; idx += 512){
                    int r, c;
                    if (idx < 256)      { r = idx >> 5;              c = idx & 31; }
                    else if (idx < 512) { r = 24 + ((idx-256) >> 5); c = idx & 31; }
                    else { int t = idx-512; r = 8 + (t >> 4); int cc = t & 15;
                           c = (cc < 8) ? cc : 16 + cc; }
                    int gh = bh + r, gw = bw + c;
                    float v = BIGF;
                    if ((unsigned)gh < HH && (unsigned)gw < WW)
                        v = __ldcg(src + gh*WW + gw);
                    sd[0][r+1][c+1] = v;
                }
            }
            __syncthreads();

            #pragma unroll
            for (int it = 0; it < 8; it++){
                const int cur = it & 1;
                bool act = (ty >= 1+it) && (ty <= 30-it) &&
                           (2*tx+1 >= 1+it) && (2*tx <= 30-it);
                if (act){
                    unsigned long long a0 = *(const unsigned long long*)&sd[cur][ty  ][2*tx];
                    unsigned long long a1 = *(const unsigned long long*)&sd[cur][ty  ][2*tx+2];
                    unsigned long long b0 = *(const unsigned long long*)&sd[cur][ty+1][2*tx];
                    unsigned long long b1 = *(const unsigned long long*)&sd[cur][ty+1][2*tx+2];
                    unsigned long long c0 = *(const unsigned long long*)&sd[cur][ty+2][2*tx];
                    unsigned long long c1 = *(const unsigned long long*)&sd[cur][ty+2][2*tx+2];

                    float2 fa0 = upk2(a0), fa1 = upk2(a1);
                    float2 fb0 = upk2(b0), fb1 = upk2(b1);
                    float2 fc0 = upk2(c0), fc1 = upk2(c1);

                    unsigned long long mixA = pk2(fa0.y, fa1.x);
                    unsigned long long mixC = pk2(fc0.y, fc1.x);

                    unsigned long long s0 = add2(a0,   cst2[0]);
                    unsigned long long s1 = add2(mixA, cst2[1]);
                    unsigned long long s2 = add2(a1,   cst2[2]);
                    unsigned long long s3 = add2(b0,   cst2[3]);
                    unsigned long long s4 = add2(b1,   cst2[4]);
                    unsigned long long s5 = add2(c0,   cst2[5]);
                    unsigned long long s6 = add2(mixC, cst2[6]);
                    unsigned long long s7 = add2(c1,   cst2[7]);

                    float2 u0 = upk2(s0), u1 = upk2(s1), u2 = upk2(s2), u3 = upk2(s3);
                    float2 u4 = upk2(s4), u5 = upk2(s5), u6 = upk2(s6), u7 = upk2(s7);

                    float v0 = fminf(fb0.y,
                               fminf(fminf(fminf(u0.x,u1.x), fminf(u2.x,u3.x)),
                                     fminf(fminf(u4.x,u5.x), fminf(u6.x,u7.x))));
                    float v1 = fminf(fb1.x,
                               fminf(fminf(fminf(u0.y,u1.y), fminf(u2.y,u3.y)),
                                     fminf(fminf(u4.y,u5.y), fminf(u6.y,u7.y))));

                    sd[cur^1][ty+1][2*tx+1] = v0;
                    sd[cur^1][ty+1][2*tx+2] = v1;
                }
                __syncthreads();
            }
            // 8 iterations (even) -> exact interior in sd[0], rows/cols [8,23]

            if (p < 31){
                if (ty >= 8 && ty < 24 && tx >= 4 && tx < 12){
                    int gh = bh + ty, gw = bw + 2*tx;
                    __stcg(dst + gh*WW + gw,     sd[0][ty+1][2*tx+1]);
                    __stcg(dst + gh*WW + gw + 1, sd[0][ty+1][2*tx+2]);
                }
                __threadfence();
            } else {
                // final phase: write output directly (heuristic + dist)
                if (ty >= 8 && ty < 24 && tx >= 4 && tx < 12){
                    int gh = bh + ty, gw = bw + 2*tx;
                    int e = endn[0]*WW + endn[1];
                    float varEnd = g_var[e];
                    float q0 = softplusf(*dl), q1 = softplusf(*gm), q2 = softplusf(*bt);
                    #pragma unroll
                    for (int b=0; b<2; b++){
                        int px = gh*WW + gw + b;
                        float om = g_omega[px];
                        float hv = q0*g_geo[px]
                                 + om*q1*(varEnd - g_var[px])
                                 + (1.0f - om)*q2*sqrtf(g_abs2[px]);
                        out[(size_t)px*10 + 0] = fmaxf(hv, 0.0f);
                        out[(size_t)px*10 + 9] = fminf(sd[0][ty+1][2*tx+1+b], BIGF);
                    }
                }
            }
        }

        if (p < 31){
            __syncthreads();
            if (tid == 0){
                atomicAdd(&g_arrive, 1u);
                unsigned target = NBLK * (unsigned)(p + 1);
                while (*((volatile unsigned*)&g_arrive) < target) __nanosleep(64);
            }
            __syncthreads();
        }
    }
}

// ---------------- launch ----------------
extern "C" void kernel_launch(void* const* d_in, const int* in_sizes, int n_in,
                              void* d_out, int out_size){
    const float* f = (const float*)d_in[0];
    float* out = (float*)d_out;

    hc_k<<<dim3(16,16), 256>>>(f, out, (const float*)d_in[4], (const float*)d_in[5],
                               (const float*)d_in[6], (const float*)d_in[7],
                               (const int*)d_in[9]);
    dist_relax_persist<<<dim3(16,16), 512>>>((const int*)d_in[8], (const int*)d_in[9],
                                             (const float*)d_in[1], (const float*)d_in[2],
                                             (const float*)d_in[3], out);
}